// round 2
// baseline (speedup 1.0000x reference)
#include <cuda_runtime.h>
#include <cuda_bf16.h>

// Problem constants (hardcoded per reference)
#define BATCH 2
#define SEQ   2048
#define DMODEL 1024
#define NHEADS 16
#define DK 64
#define M_TOK (BATCH*SEQ)          // 4096

// Scratch (no allocations allowed -> __device__ globals)
__device__ float g_q[BATCH*NHEADS*SEQ*DK];      // 16 MB
__device__ float g_k[BATCH*NHEADS*SEQ*DK];      // 16 MB
__device__ float g_v[BATCH*NHEADS*SEQ*DK];      // 16 MB
__device__ float g_attn[M_TOK*DMODEL];          // 16 MB

// ---------------------------------------------------------------------------
// SGEMM: C = A @ B^T + bias.  A: [M,K] row-major, B: [N,K] row-major.
// mode 0: scatter QKV output into g_q/g_k/g_v ([B,H,S,Dk] layout)
// mode 1: plain write C[row*N+col]
// Tile: 128x128x8, 256 threads, 8x8 per-thread microtile.
// Requires M%128==0, N%128==0, K%8==0 (true for all our shapes).
// ---------------------------------------------------------------------------
#define BM 128
#define BN 128
#define BK 8

__global__ __launch_bounds__(256)
void sgemm128(const float* __restrict__ A, const float* __restrict__ B,
              const float* __restrict__ bias, float* __restrict__ C,
              int M, int N, int K, int mode)
{
    __shared__ float As[BK][BM];
    __shared__ float Bs[BK][BN];

    const int tid = threadIdx.x;
    const int bm = blockIdx.y, bn = blockIdx.x;

    const int lrow = tid >> 1;           // 0..127 (load row within tile)
    const int lcol = (tid & 1) * 4;      // 0 or 4 (k offset of float4)

    const float* Aptr = A + (size_t)(bm*BM + lrow)*K + lcol;
    const float* Bptr = B + (size_t)(bn*BN + lrow)*K + lcol;

    const int ty = tid >> 4;             // 0..15  -> rows ty*8..ty*8+7
    const int tx = tid & 15;             // 0..15  -> cols tx*8..tx*8+7

    float acc[8][8];
#pragma unroll
    for (int i = 0; i < 8; i++)
#pragma unroll
        for (int j = 0; j < 8; j++) acc[i][j] = 0.f;

    for (int k0 = 0; k0 < K; k0 += BK) {
        float4 av = *(const float4*)(Aptr + k0);
        float4 bv = *(const float4*)(Bptr + k0);
        As[lcol+0][lrow] = av.x; As[lcol+1][lrow] = av.y;
        As[lcol+2][lrow] = av.z; As[lcol+3][lrow] = av.w;
        Bs[lcol+0][lrow] = bv.x; Bs[lcol+1][lrow] = bv.y;
        Bs[lcol+2][lrow] = bv.z; Bs[lcol+3][lrow] = bv.w;
        __syncthreads();

#pragma unroll
        for (int k = 0; k < BK; k++) {
            float ra[8], rb[8];
#pragma unroll
            for (int i = 0; i < 8; i++) ra[i] = As[k][ty*8 + i];
#pragma unroll
            for (int j = 0; j < 8; j++) rb[j] = Bs[k][tx*8 + j];
#pragma unroll
            for (int i = 0; i < 8; i++)
#pragma unroll
                for (int j = 0; j < 8; j++)
                    acc[i][j] = fmaf(ra[i], rb[j], acc[i][j]);
        }
        __syncthreads();
    }

    // Epilogue
#pragma unroll
    for (int i = 0; i < 8; i++) {
        const int row = bm*BM + ty*8 + i;
#pragma unroll
        for (int j = 0; j < 8; j++) {
            const int col = bn*BN + tx*8 + j;
            float v = acc[i][j] + bias[col];
            if (mode == 0) {
                // col in [0,3072): sel = q/k/v, then [B,H,S,Dk]
                const int sel = col >> 10;
                const int d2  = col & 1023;
                const int h   = d2 >> 6;
                const int dk  = d2 & 63;
                const int b   = row >> 11;   // /SEQ
                const int s   = row & 2047;
                float* dst = (sel == 0) ? g_q : (sel == 1) ? g_k : g_v;
                dst[(((b << 4) + h) * SEQ + s) * DK + dk] = v;
            } else {
                C[(size_t)row * N + col] = v;
            }
        }
    }
}

// ---------------------------------------------------------------------------
// Flash attention (causal), fp32.
// Grid: (SEQ/64, B*H).  Block: 256 threads.
// Each query row handled by 4 consecutive lanes; each lane owns 16 head-dims
// arranged as 4 float4 chunks at chunk index (jj*4 + sub) to keep smem
// accesses conflict-free. Q fragment + scores + O accumulator live in regs;
// K and V tiles (64x64) live in smem.
// ---------------------------------------------------------------------------
__global__ __launch_bounds__(256)
void flash_attn_kernel()
{
    const int qt  = blockIdx.x;          // query tile 0..31
    const int bh  = blockIdx.y;          // 0..31
    const int tid = threadIdx.x;
    const int row = tid >> 2;            // 0..63
    const int sub = tid & 3;             // 0..3
    const int qglob = qt*64 + row;

    __shared__ float Ks[64][68];
    __shared__ float Vs[64][68];

    // Load Q fragment into registers (16 floats: chunks jj*4+sub)
    const float* qbase = g_q + (size_t)(bh*SEQ + qglob)*DK;
    float qf[16];
#pragma unroll
    for (int jj = 0; jj < 4; jj++) {
        float4 v = *(const float4*)(qbase + (jj*4 + sub)*4);
        qf[jj*4+0] = v.x; qf[jj*4+1] = v.y; qf[jj*4+2] = v.z; qf[jj*4+3] = v.w;
    }

    float m = -1e30f, l = 0.f;
    float O[16];
#pragma unroll
    for (int i = 0; i < 16; i++) O[i] = 0.f;

    const float scale = 0.125f;          // 1/sqrt(64)

    const int ldr = tid >> 2;            // load row
    const int ldc = (tid & 3) * 4;       // load chunk base (4 chunks per thread)

    for (int kt = 0; kt <= qt; kt++) {
        __syncthreads();                 // protect previous tile use
        {
            const float* kb = g_k + (size_t)(bh*SEQ + kt*64 + ldr)*DK;
            const float* vb = g_v + (size_t)(bh*SEQ + kt*64 + ldr)*DK;
#pragma unroll
            for (int j = 0; j < 4; j++) {
                *(float4*)(&Ks[ldr][(ldc+j)*4]) = *(const float4*)(kb + (ldc+j)*4);
                *(float4*)(&Vs[ldr][(ldc+j)*4]) = *(const float4*)(vb + (ldc+j)*4);
            }
        }
        __syncthreads();

        // Scores: every lane computes partial dot over its 16 dims for all
        // 64 keys, then a 4-lane butterfly gives every lane all 64 full dots.
        float s[64];
#pragma unroll
        for (int key = 0; key < 64; key++) {
            float a = 0.f;
#pragma unroll
            for (int jj = 0; jj < 4; jj++) {
                float4 kv = *(const float4*)(&Ks[key][(jj*4 + sub)*4]);
                a = fmaf(qf[jj*4+0], kv.x, a);
                a = fmaf(qf[jj*4+1], kv.y, a);
                a = fmaf(qf[jj*4+2], kv.z, a);
                a = fmaf(qf[jj*4+3], kv.w, a);
            }
            a += __shfl_xor_sync(0xffffffffu, a, 1);
            a += __shfl_xor_sync(0xffffffffu, a, 2);
            s[key] = a * scale;
        }

        // Causal mask on diagonal tile
        if (kt == qt) {
#pragma unroll
            for (int key = 0; key < 64; key++)
                if (kt*64 + key > qglob) s[key] = -1e30f;
        }

        // Online softmax update
        float mt = m;
#pragma unroll
        for (int key = 0; key < 64; key++) mt = fmaxf(mt, s[key]);
        const float corr = __expf(m - mt);
        m = mt;
        l *= corr;
#pragma unroll
        for (int i = 0; i < 16; i++) O[i] *= corr;

        float psum = 0.f;
#pragma unroll
        for (int key = 0; key < 64; key++) {
            s[key] = __expf(s[key] - m);
            psum += s[key];
        }
        l += psum;

        // O += P @ V  (each lane: its 16 dims)
#pragma unroll
        for (int key = 0; key < 64; key++) {
            const float pv = s[key];
#pragma unroll
            for (int jj = 0; jj < 4; jj++) {
                float4 vv = *(const float4*)(&Vs[key][(jj*4 + sub)*4]);
                O[jj*4+0] = fmaf(pv, vv.x, O[jj*4+0]);
                O[jj*4+1] = fmaf(pv, vv.y, O[jj*4+1]);
                O[jj*4+2] = fmaf(pv, vv.z, O[jj*4+2]);
                O[jj*4+3] = fmaf(pv, vv.w, O[jj*4+3]);
            }
        }
    }

    // Finalize and write to [B,S,D] layout for the O-projection GEMM
    const float inv = 1.f / l;
    const int b = bh >> 4, h = bh & 15;
    float* ob = g_attn + (size_t)(b*SEQ + qglob)*DMODEL + h*DK;
#pragma unroll
    for (int jj = 0; jj < 4; jj++) {
        float4 v;
        v.x = O[jj*4+0]*inv; v.y = O[jj*4+1]*inv;
        v.z = O[jj*4+2]*inv; v.w = O[jj*4+3]*inv;
        *(float4*)(ob + (jj*4 + sub)*4) = v;
    }
}

// ---------------------------------------------------------------------------
// Launch
// Inputs (metadata order): x, mask, w_qkv_w, w_qkv_b, w_o_w, w_o_b
// ---------------------------------------------------------------------------
extern "C" void kernel_launch(void* const* d_in, const int* in_sizes, int n_in,
                              void* d_out, int out_size)
{
    const float* x      = (const float*)d_in[0];
    // d_in[1] = mask (causal, implicit in kernel)
    const float* wqkv   = (const float*)d_in[2];
    const float* bqkv   = (const float*)d_in[3];
    const float* wo     = (const float*)d_in[4];
    const float* bo     = (const float*)d_in[5];
    float* out = (float*)d_out;

    float* attn_ptr;
    cudaGetSymbolAddress((void**)&attn_ptr, g_attn);

    // 1) QKV projection, scattered into g_q/g_k/g_v
    {
        dim3 grid(3*DMODEL/BN, M_TOK/BM);   // (24, 32)
        sgemm128<<<grid, 256>>>(x, wqkv, bqkv, nullptr, M_TOK, 3*DMODEL, DMODEL, 0);
    }
    // 2) Causal flash attention -> g_attn [B,S,D]
    {
        dim3 grid(SEQ/64, BATCH*NHEADS);    // (32, 32)
        flash_attn_kernel<<<grid, 256>>>();
    }
    // 3) Output projection -> d_out
    {
        dim3 grid(DMODEL/BN, M_TOK/BM);     // (8, 32)
        sgemm128<<<grid, 256>>>(attn_ptr, wo, bo, out, M_TOK, DMODEL, DMODEL, 1);
    }
}

// round 4
// speedup vs baseline: 1.3431x; 1.3431x over previous
#include <cuda_runtime.h>
#include <cuda_bf16.h>
#include <cstdint>

// Problem constants
#define BATCH 2
#define SEQ   2048
#define DMODEL 1024
#define NHEADS 16
#define DK 64
#define M_TOK (BATCH*SEQ)          // 4096

// Scratch (no allocations allowed -> __device__ globals)
__device__ float g_q[BATCH*NHEADS*SEQ*DK];      // 16 MB
__device__ float g_k[BATCH*NHEADS*SEQ*DK];      // 16 MB
__device__ float g_v[BATCH*NHEADS*SEQ*DK];      // 16 MB
__device__ float g_attn[M_TOK*DMODEL];          // 16 MB

// ---------------------------------------------------------------------------
// tf32 helpers (legacy mma.sync path — compiles for plain compute_103)
// ---------------------------------------------------------------------------
__device__ __forceinline__ float to_tf32(float x) {
    uint32_t u;
    asm("cvt.rna.tf32.f32 %0, %1;" : "=r"(u) : "f"(x));
    return __uint_as_float(u);
}

__device__ __forceinline__ void mma_tf32_16x8x8(
    float& d0, float& d1, float& d2, float& d3,
    uint32_t a0, uint32_t a1, uint32_t a2, uint32_t a3,
    uint32_t b0, uint32_t b1)
{
    asm volatile(
        "mma.sync.aligned.m16n8k8.row.col.f32.tf32.tf32.f32 "
        "{%0,%1,%2,%3}, {%4,%5,%6,%7}, {%8,%9}, {%0,%1,%2,%3};"
        : "+f"(d0), "+f"(d1), "+f"(d2), "+f"(d3)
        : "r"(a0), "r"(a1), "r"(a2), "r"(a3), "r"(b0), "r"(b1));
}

// ===========================================================================
// tf32 tensor-core GEMM: C = A @ B^T + bias.
// A: [M,K] row-major fp32, B: [N,K] row-major fp32. M,N % 128 == 0, K % 16 == 0.
// 128x128 tile, BK=16, 256 threads (8 warps, 2x4 warp grid, 64x32 per warp).
// Operands staged to smem as [k][m] / [k][n] (stride 136 -> conflict-free
// fragment loads), converted to tf32 (round-to-nearest) at staging time.
// mode 0: scatter into g_q/g_k/g_v ([B,H,S,Dk]); mode 1: plain C write.
// ===========================================================================
#define BM 128
#define BN 128
#define BK 16
#define LDSTR 136      // smem row stride in floats (136 % 32 == 8 -> no conflicts)

__global__ __launch_bounds__(256)
void mma_gemm(const float* __restrict__ A, const float* __restrict__ B,
              const float* __restrict__ bias, float* __restrict__ C,
              int M, int N, int K, int mode)
{
    __shared__ float As[BK][LDSTR];   // As[k][m]
    __shared__ float Bs[BK][LDSTR];   // Bs[k][n]

    const int tid = threadIdx.x;
    const int wid = tid >> 5;
    const int lane = tid & 31;
    const int gid = lane >> 2;        // groupID 0..7
    const int tig = lane & 3;         // thread-in-group 0..3
    const int warpM = wid >> 2;       // 0..1
    const int warpN = wid & 3;        // 0..3
    const int bm = blockIdx.y, bn = blockIdx.x;

    const float* Abase = A + (size_t)(bm*BM)*K;
    const float* Bbase = B + (size_t)(bn*BN)*K;

    // Accumulators: 4 m-tiles x 4 n-tiles x 4 regs
    float acc[4][4][4];
#pragma unroll
    for (int i = 0; i < 4; i++)
#pragma unroll
        for (int j = 0; j < 4; j++)
#pragma unroll
            for (int r = 0; r < 4; r++) acc[i][j][r] = 0.f;

    for (int k0 = 0; k0 < K; k0 += BK) {
        __syncthreads();
        // Stage 128x16 A and B tiles, transposed, tf32-rounded.
        // 512 float4 per operand; 256 threads -> 2 each.
#pragma unroll
        for (int t = 0; t < 2; t++) {
            const int f = tid + t*256;
            const int row = f >> 2;           // 0..127
            const int kq  = f & 3;            // float4 index along K
            float4 av = *(const float4*)(Abase + (size_t)row*K + k0 + kq*4);
            float4 bv = *(const float4*)(Bbase + (size_t)row*K + k0 + kq*4);
            As[kq*4+0][row] = to_tf32(av.x);
            As[kq*4+1][row] = to_tf32(av.y);
            As[kq*4+2][row] = to_tf32(av.z);
            As[kq*4+3][row] = to_tf32(av.w);
            Bs[kq*4+0][row] = to_tf32(bv.x);
            Bs[kq*4+1][row] = to_tf32(bv.y);
            Bs[kq*4+2][row] = to_tf32(bv.z);
            Bs[kq*4+3][row] = to_tf32(bv.w);
        }
        __syncthreads();

#pragma unroll
        for (int ks = 0; ks < 2; ks++) {
            const int kb = ks*8;
            // B fragments: 4 n-tiles x 2 regs
            uint32_t bf[4][2];
#pragma unroll
            for (int nt = 0; nt < 4; nt++) {
                const int col = warpN*32 + nt*8 + gid;
                bf[nt][0] = __float_as_uint(Bs[kb + tig    ][col]);
                bf[nt][1] = __float_as_uint(Bs[kb + tig + 4][col]);
            }
            // A fragments + mma
#pragma unroll
            for (int mt = 0; mt < 4; mt++) {
                const int row = warpM*64 + mt*16 + gid;
                uint32_t a0 = __float_as_uint(As[kb + tig    ][row    ]);
                uint32_t a1 = __float_as_uint(As[kb + tig    ][row + 8]);
                uint32_t a2 = __float_as_uint(As[kb + tig + 4][row    ]);
                uint32_t a3 = __float_as_uint(As[kb + tig + 4][row + 8]);
#pragma unroll
                for (int nt = 0; nt < 4; nt++) {
                    mma_tf32_16x8x8(acc[mt][nt][0], acc[mt][nt][1],
                                    acc[mt][nt][2], acc[mt][nt][3],
                                    a0, a1, a2, a3, bf[nt][0], bf[nt][1]);
                }
            }
        }
    }

    // Epilogue: fragment layout c0,c1 -> (row, col..col+1); c2,c3 -> (row+8, ..)
#pragma unroll
    for (int mt = 0; mt < 4; mt++) {
        const int row0 = bm*BM + warpM*64 + mt*16 + gid;
#pragma unroll
        for (int nt = 0; nt < 4; nt++) {
            const int col = bn*BN + warpN*32 + nt*8 + tig*2;
            const float bz0 = bias[col], bz1 = bias[col+1];
#pragma unroll
            for (int half = 0; half < 2; half++) {
                const int row = row0 + half*8;
                float v0 = acc[mt][nt][half*2+0] + bz0;
                float v1 = acc[mt][nt][half*2+1] + bz1;
                if (mode == 1) {
                    *(float2*)(C + (size_t)row*N + col) = make_float2(v0, v1);
                } else {
                    const int sel = col >> 10;
                    const int d2  = col & 1023;
                    const int h   = d2 >> 6;
                    const int dk  = d2 & 63;
                    const int b   = row >> 11;
                    const int s   = row & 2047;
                    float* dst = (sel == 0) ? g_q : (sel == 1) ? g_k : g_v;
                    *(float2*)(dst + ((size_t)(((b<<4)+h)*SEQ + s))*DK + dk)
                        = make_float2(v0, v1);
                }
            }
        }
    }
}

// ---------------------------------------------------------------------------
// Flash attention (causal), fp32 scalar (unchanged from passing baseline).
// ---------------------------------------------------------------------------
__global__ __launch_bounds__(256)
void flash_attn_kernel()
{
    const int qt  = blockIdx.x;
    const int bh  = blockIdx.y;
    const int tid = threadIdx.x;
    const int row = tid >> 2;
    const int sub = tid & 3;
    const int qglob = qt*64 + row;

    __shared__ float Ks[64][68];
    __shared__ float Vs[64][68];

    const float* qbase = g_q + (size_t)(bh*SEQ + qglob)*DK;
    float qf[16];
#pragma unroll
    for (int jj = 0; jj < 4; jj++) {
        float4 v = *(const float4*)(qbase + (jj*4 + sub)*4);
        qf[jj*4+0] = v.x; qf[jj*4+1] = v.y; qf[jj*4+2] = v.z; qf[jj*4+3] = v.w;
    }

    float m = -1e30f, l = 0.f;
    float O[16];
#pragma unroll
    for (int i = 0; i < 16; i++) O[i] = 0.f;

    const float scale = 0.125f;
    const int ldr = tid >> 2;
    const int ldc = (tid & 3) * 4;

    for (int kt = 0; kt <= qt; kt++) {
        __syncthreads();
        {
            const float* kb = g_k + (size_t)(bh*SEQ + kt*64 + ldr)*DK;
            const float* vb = g_v + (size_t)(bh*SEQ + kt*64 + ldr)*DK;
#pragma unroll
            for (int j = 0; j < 4; j++) {
                *(float4*)(&Ks[ldr][(ldc+j)*4]) = *(const float4*)(kb + (ldc+j)*4);
                *(float4*)(&Vs[ldr][(ldc+j)*4]) = *(const float4*)(vb + (ldc+j)*4);
            }
        }
        __syncthreads();

        float s[64];
#pragma unroll
        for (int key = 0; key < 64; key++) {
            float a = 0.f;
#pragma unroll
            for (int jj = 0; jj < 4; jj++) {
                float4 kv = *(const float4*)(&Ks[key][(jj*4 + sub)*4]);
                a = fmaf(qf[jj*4+0], kv.x, a);
                a = fmaf(qf[jj*4+1], kv.y, a);
                a = fmaf(qf[jj*4+2], kv.z, a);
                a = fmaf(qf[jj*4+3], kv.w, a);
            }
            a += __shfl_xor_sync(0xffffffffu, a, 1);
            a += __shfl_xor_sync(0xffffffffu, a, 2);
            s[key] = a * scale;
        }

        if (kt == qt) {
#pragma unroll
            for (int key = 0; key < 64; key++)
                if (kt*64 + key > qglob) s[key] = -1e30f;
        }

        float mt = m;
#pragma unroll
        for (int key = 0; key < 64; key++) mt = fmaxf(mt, s[key]);
        const float corr = __expf(m - mt);
        m = mt;
        l *= corr;
#pragma unroll
        for (int i = 0; i < 16; i++) O[i] *= corr;

        float psum = 0.f;
#pragma unroll
        for (int key = 0; key < 64; key++) {
            s[key] = __expf(s[key] - m);
            psum += s[key];
        }
        l += psum;

#pragma unroll
        for (int key = 0; key < 64; key++) {
            const float pv = s[key];
#pragma unroll
            for (int jj = 0; jj < 4; jj++) {
                float4 vv = *(const float4*)(&Vs[key][(jj*4 + sub)*4]);
                O[jj*4+0] = fmaf(pv, vv.x, O[jj*4+0]);
                O[jj*4+1] = fmaf(pv, vv.y, O[jj*4+1]);
                O[jj*4+2] = fmaf(pv, vv.z, O[jj*4+2]);
                O[jj*4+3] = fmaf(pv, vv.w, O[jj*4+3]);
            }
        }
    }

    const float inv = 1.f / l;
    const int b = bh >> 4, h = bh & 15;
    float* ob = g_attn + (size_t)(b*SEQ + qglob)*DMODEL + h*DK;
#pragma unroll
    for (int jj = 0; jj < 4; jj++) {
        float4 v;
        v.x = O[jj*4+0]*inv; v.y = O[jj*4+1]*inv;
        v.z = O[jj*4+2]*inv; v.w = O[jj*4+3]*inv;
        *(float4*)(ob + (jj*4 + sub)*4) = v;
    }
}

// ---------------------------------------------------------------------------
// Launch.  Inputs: x, mask, w_qkv_w, w_qkv_b, w_o_w, w_o_b
// ---------------------------------------------------------------------------
extern "C" void kernel_launch(void* const* d_in, const int* in_sizes, int n_in,
                              void* d_out, int out_size)
{
    const float* x      = (const float*)d_in[0];
    const float* wqkv   = (const float*)d_in[2];
    const float* bqkv   = (const float*)d_in[3];
    const float* wo     = (const float*)d_in[4];
    const float* bo     = (const float*)d_in[5];
    float* out = (float*)d_out;

    float* attn_ptr;
    cudaGetSymbolAddress((void**)&attn_ptr, g_attn);

    // 1) QKV projection (tf32 mma.sync) -> g_q/g_k/g_v
    {
        dim3 grid(3*DMODEL/BN, M_TOK/BM);   // (24, 32)
        mma_gemm<<<grid, 256>>>(x, wqkv, bqkv, nullptr, M_TOK, 3*DMODEL, DMODEL, 0);
    }
    // 2) Causal flash attention -> g_attn [B,S,D]
    {
        dim3 grid(SEQ/64, BATCH*NHEADS);    // (32, 32)
        flash_attn_kernel<<<grid, 256>>>();
    }
    // 3) Output projection (tf32 mma.sync) -> d_out
    {
        dim3 grid(DMODEL/BN, M_TOK/BM);     // (8, 32)
        mma_gemm<<<grid, 256>>>(attn_ptr, wo, bo, out, M_TOK, DMODEL, DMODEL, 1);
    }
}

// round 6
// speedup vs baseline: 3.8999x; 2.9038x over previous
#include <cuda_runtime.h>
#include <cuda_bf16.h>
#include <cstdint>

// Problem constants
#define BATCH 2
#define SEQ   2048
#define DMODEL 1024
#define NHEADS 16
#define DK 64
#define M_TOK (BATCH*SEQ)          // 4096

// Scratch (no allocations allowed -> __device__ globals)
__device__ float g_q[BATCH*NHEADS*SEQ*DK];      // 16 MB
__device__ float g_k[BATCH*NHEADS*SEQ*DK];      // 16 MB
__device__ float g_v[BATCH*NHEADS*SEQ*DK];      // 16 MB
__device__ float g_attn[M_TOK*DMODEL];          // 16 MB

// ---------------------------------------------------------------------------
// tf32 helpers (legacy mma.sync path — compiles for plain compute_103)
// ---------------------------------------------------------------------------
__device__ __forceinline__ float to_tf32(float x) {
    uint32_t u;
    asm("cvt.rna.tf32.f32 %0, %1;" : "=r"(u) : "f"(x));
    return __uint_as_float(u);
}
__device__ __forceinline__ uint32_t to_tf32_u(float x) {
    uint32_t u;
    asm("cvt.rna.tf32.f32 %0, %1;" : "=r"(u) : "f"(x));
    return u;
}

__device__ __forceinline__ void mma_tf32_16x8x8(
    float& d0, float& d1, float& d2, float& d3,
    uint32_t a0, uint32_t a1, uint32_t a2, uint32_t a3,
    uint32_t b0, uint32_t b1)
{
    asm volatile(
        "mma.sync.aligned.m16n8k8.row.col.f32.tf32.tf32.f32 "
        "{%0,%1,%2,%3}, {%4,%5,%6,%7}, {%8,%9}, {%0,%1,%2,%3};"
        : "+f"(d0), "+f"(d1), "+f"(d2), "+f"(d3)
        : "r"(a0), "r"(a1), "r"(a2), "r"(a3), "r"(b0), "r"(b1));
}

#define SHFL(v, s)     __shfl_sync(0xffffffffu, v, s)
#define SHFL_XOR(v, m) __shfl_xor_sync(0xffffffffu, v, m)

// ===========================================================================
// tf32 tensor-core GEMM (unchanged from Round 4): C = A @ B^T + bias.
// ===========================================================================
#define BM 128
#define BN 128
#define BK 16
#define LDSTR 136

__global__ __launch_bounds__(256)
void mma_gemm(const float* __restrict__ A, const float* __restrict__ B,
              const float* __restrict__ bias, float* __restrict__ C,
              int M, int N, int K, int mode)
{
    __shared__ float As[BK][LDSTR];
    __shared__ float Bs[BK][LDSTR];

    const int tid = threadIdx.x;
    const int wid = tid >> 5;
    const int lane = tid & 31;
    const int gid = lane >> 2;
    const int tig = lane & 3;
    const int warpM = wid >> 2;
    const int warpN = wid & 3;
    const int bm = blockIdx.y, bn = blockIdx.x;

    const float* Abase = A + (size_t)(bm*BM)*K;
    const float* Bbase = B + (size_t)(bn*BN)*K;

    float acc[4][4][4];
#pragma unroll
    for (int i = 0; i < 4; i++)
#pragma unroll
        for (int j = 0; j < 4; j++)
#pragma unroll
            for (int r = 0; r < 4; r++) acc[i][j][r] = 0.f;

    for (int k0 = 0; k0 < K; k0 += BK) {
        __syncthreads();
#pragma unroll
        for (int t = 0; t < 2; t++) {
            const int f = tid + t*256;
            const int row = f >> 2;
            const int kq  = f & 3;
            float4 av = *(const float4*)(Abase + (size_t)row*K + k0 + kq*4);
            float4 bv = *(const float4*)(Bbase + (size_t)row*K + k0 + kq*4);
            As[kq*4+0][row] = to_tf32(av.x);
            As[kq*4+1][row] = to_tf32(av.y);
            As[kq*4+2][row] = to_tf32(av.z);
            As[kq*4+3][row] = to_tf32(av.w);
            Bs[kq*4+0][row] = to_tf32(bv.x);
            Bs[kq*4+1][row] = to_tf32(bv.y);
            Bs[kq*4+2][row] = to_tf32(bv.z);
            Bs[kq*4+3][row] = to_tf32(bv.w);
        }
        __syncthreads();

#pragma unroll
        for (int ks = 0; ks < 2; ks++) {
            const int kb = ks*8;
            uint32_t bf[4][2];
#pragma unroll
            for (int nt = 0; nt < 4; nt++) {
                const int col = warpN*32 + nt*8 + gid;
                bf[nt][0] = __float_as_uint(Bs[kb + tig    ][col]);
                bf[nt][1] = __float_as_uint(Bs[kb + tig + 4][col]);
            }
#pragma unroll
            for (int mt = 0; mt < 4; mt++) {
                const int row = warpM*64 + mt*16 + gid;
                uint32_t a0 = __float_as_uint(As[kb + tig    ][row    ]);
                uint32_t a1 = __float_as_uint(As[kb + tig    ][row + 8]);
                uint32_t a2 = __float_as_uint(As[kb + tig + 4][row    ]);
                uint32_t a3 = __float_as_uint(As[kb + tig + 4][row + 8]);
#pragma unroll
                for (int nt = 0; nt < 4; nt++) {
                    mma_tf32_16x8x8(acc[mt][nt][0], acc[mt][nt][1],
                                    acc[mt][nt][2], acc[mt][nt][3],
                                    a0, a1, a2, a3, bf[nt][0], bf[nt][1]);
                }
            }
        }
    }

#pragma unroll
    for (int mt = 0; mt < 4; mt++) {
        const int row0 = bm*BM + warpM*64 + mt*16 + gid;
#pragma unroll
        for (int nt = 0; nt < 4; nt++) {
            const int col = bn*BN + warpN*32 + nt*8 + tig*2;
            const float bz0 = bias[col], bz1 = bias[col+1];
#pragma unroll
            for (int half = 0; half < 2; half++) {
                const int row = row0 + half*8;
                float v0 = acc[mt][nt][half*2+0] + bz0;
                float v1 = acc[mt][nt][half*2+1] + bz1;
                if (mode == 1) {
                    *(float2*)(C + (size_t)row*N + col) = make_float2(v0, v1);
                } else {
                    const int sel = col >> 10;
                    const int d2  = col & 1023;
                    const int h   = d2 >> 6;
                    const int dk  = d2 & 63;
                    const int b   = row >> 11;
                    const int s   = row & 2047;
                    float* dst = (sel == 0) ? g_q : (sel == 1) ? g_k : g_v;
                    *(float2*)(dst + ((size_t)(((b<<4)+h)*SEQ + s))*DK + dk)
                        = make_float2(v0, v1);
                }
            }
        }
    }
}

// ===========================================================================
// Tensor-core causal flash attention (tf32 mma.sync).
// Grid: (SEQ/128, B*H). Block: 256 threads = 8 warps; warp w owns q rows
// [w*16, w*16+16) of the 128-row q tile. K-tiles of 64 keys staged in smem.
// Scores/P live in C-fragment registers; PV uses a quad-shuffle permutation
// to build A-fragments of P (m16n8k8 C->A layout fix, no smem round-trip).
// ===========================================================================
__global__ __launch_bounds__(256, 2)
void flash_attn_mma()
{
    const int qt  = blockIdx.x;          // 0..15
    const int bh  = blockIdx.y;          // 0..31
    const int tid = threadIdx.x;
    const int w    = tid >> 5;
    const int lane = tid & 31;
    const int gid  = lane >> 2;          // 0..7
    const int tig  = lane & 3;           // 0..3

    __shared__ float Ks[64][68];         // stride 68: QK B-frag banks 4*gid+tig
    __shared__ float Vs[64][72];         // stride 72: PV B-frag banks 8*tig+gid

    const int r0  = w*16 + gid;          // local q row (and r0+8)
    const int qg0 = qt*128 + r0;         // global q row
    const int qg1 = qg0 + 8;

    // Q fragments, scaled by 1/sqrt(DK)=0.125 (exact), tf32-rounded.
    const float* qb = g_q + (size_t)(bh*SEQ + qt*128)*DK;
    uint32_t qa[8][4];
#pragma unroll
    for (int ks = 0; ks < 8; ks++) {
        qa[ks][0] = to_tf32_u(qb[(size_t)r0*DK     + ks*8 + tig    ] * 0.125f);
        qa[ks][1] = to_tf32_u(qb[(size_t)(r0+8)*DK + ks*8 + tig    ] * 0.125f);
        qa[ks][2] = to_tf32_u(qb[(size_t)r0*DK     + ks*8 + tig + 4] * 0.125f);
        qa[ks][3] = to_tf32_u(qb[(size_t)(r0+8)*DK + ks*8 + tig + 4] * 0.125f);
    }

    float o[8][4];
#pragma unroll
    for (int dt = 0; dt < 8; dt++)
#pragma unroll
        for (int r = 0; r < 4; r++) o[dt][r] = 0.f;
    float m0 = -1e30f, m1 = -1e30f, l0 = 0.f, l1 = 0.f;

    const int nkt = 2*qt + 2;            // 64-key tiles covering causal range
    const float* kb0 = g_k + (size_t)bh*SEQ*DK;
    const float* vb0 = g_v + (size_t)bh*SEQ*DK;

    for (int kt = 0; kt < nkt; kt++) {
        __syncthreads();
        // Stage K,V 64x64 tiles (tf32-rounded). 1024 float4 each, 4/thread.
        {
            const float* kb = kb0 + (size_t)kt*64*DK;
            const float* vb = vb0 + (size_t)kt*64*DK;
#pragma unroll
            for (int i = 0; i < 4; i++) {
                const int f = tid + i*256;
                const int row = f >> 4;
                const int q4  = f & 15;
                float4 kv = *(const float4*)(kb + row*DK + q4*4);
                float4 vv = *(const float4*)(vb + row*DK + q4*4);
                float4 kt4, vt4;
                kt4.x = to_tf32(kv.x); kt4.y = to_tf32(kv.y);
                kt4.z = to_tf32(kv.z); kt4.w = to_tf32(kv.w);
                vt4.x = to_tf32(vv.x); vt4.y = to_tf32(vv.y);
                vt4.z = to_tf32(vv.z); vt4.w = to_tf32(vv.w);
                *(float4*)(&Ks[row][q4*4]) = kt4;
                *(float4*)(&Vs[row][q4*4]) = vt4;
            }
        }
        __syncthreads();

        // ---- S = Q K^T (scaled) ----
        float s[8][4];
#pragma unroll
        for (int nt = 0; nt < 8; nt++)
#pragma unroll
            for (int r = 0; r < 4; r++) s[nt][r] = 0.f;

#pragma unroll
        for (int ks = 0; ks < 8; ks++) {
#pragma unroll
            for (int nt = 0; nt < 8; nt++) {
                const uint32_t b0 = __float_as_uint(Ks[nt*8 + gid][ks*8 + tig    ]);
                const uint32_t b1 = __float_as_uint(Ks[nt*8 + gid][ks*8 + tig + 4]);
                mma_tf32_16x8x8(s[nt][0], s[nt][1], s[nt][2], s[nt][3],
                                qa[ks][0], qa[ks][1], qa[ks][2], qa[ks][3], b0, b1);
            }
        }

        // ---- causal mask (only the last two tiles can cross the diagonal) ----
        if (kt >= 2*qt) {
#pragma unroll
            for (int nt = 0; nt < 8; nt++) {
                const int kg = kt*64 + nt*8 + 2*tig;
                if (kg     > qg0) s[nt][0] = -1e30f;
                if (kg + 1 > qg0) s[nt][1] = -1e30f;
                if (kg     > qg1) s[nt][2] = -1e30f;
                if (kg + 1 > qg1) s[nt][3] = -1e30f;
            }
        }

        // ---- online softmax ----
        float t0 = -1e30f, t1 = -1e30f;
#pragma unroll
        for (int nt = 0; nt < 8; nt++) {
            t0 = fmaxf(t0, fmaxf(s[nt][0], s[nt][1]));
            t1 = fmaxf(t1, fmaxf(s[nt][2], s[nt][3]));
        }
        t0 = fmaxf(t0, SHFL_XOR(t0, 1)); t0 = fmaxf(t0, SHFL_XOR(t0, 2));
        t1 = fmaxf(t1, SHFL_XOR(t1, 1)); t1 = fmaxf(t1, SHFL_XOR(t1, 2));
        const float m0n = fmaxf(m0, t0), m1n = fmaxf(m1, t1);
        const float c0 = __expf(m0 - m0n), c1 = __expf(m1 - m1n);
        m0 = m0n; m1 = m1n;

        float sum0 = 0.f, sum1 = 0.f;
#pragma unroll
        for (int nt = 0; nt < 8; nt++) {
            float p0 = __expf(s[nt][0] - m0);
            float p1 = __expf(s[nt][1] - m0);
            float p2 = __expf(s[nt][2] - m1);
            float p3 = __expf(s[nt][3] - m1);
            sum0 += p0 + p1; sum1 += p2 + p3;
            s[nt][0] = __uint_as_float(to_tf32_u(p0));
            s[nt][1] = __uint_as_float(to_tf32_u(p1));
            s[nt][2] = __uint_as_float(to_tf32_u(p2));
            s[nt][3] = __uint_as_float(to_tf32_u(p3));
        }
        sum0 += SHFL_XOR(sum0, 1); sum0 += SHFL_XOR(sum0, 2);
        sum1 += SHFL_XOR(sum1, 1); sum1 += SHFL_XOR(sum1, 2);
        l0 = l0*c0 + sum0;
        l1 = l1*c1 + sum1;
#pragma unroll
        for (int dt = 0; dt < 8; dt++) {
            o[dt][0] *= c0; o[dt][1] *= c0;
            o[dt][2] *= c1; o[dt][3] *= c1;
        }

        // ---- O += P V: build P A-fragments via quad shuffle ----
        const int srcA = (lane & ~3) | (tig >> 1);
        const int srcB = srcA + 2;
        const bool odd = (tig & 1);
#pragma unroll
        for (int kp = 0; kp < 8; kp++) {
            const float x0 = SHFL(s[kp][0], srcA);
            const float x1 = SHFL(s[kp][1], srcA);
            const float x2 = SHFL(s[kp][2], srcA);
            const float x3 = SHFL(s[kp][3], srcA);
            const float y0 = SHFL(s[kp][0], srcB);
            const float y1 = SHFL(s[kp][1], srcB);
            const float y2 = SHFL(s[kp][2], srcB);
            const float y3 = SHFL(s[kp][3], srcB);
            const uint32_t a0 = __float_as_uint(odd ? x1 : x0);
            const uint32_t a1 = __float_as_uint(odd ? x3 : x2);
            const uint32_t a2 = __float_as_uint(odd ? y1 : y0);
            const uint32_t a3 = __float_as_uint(odd ? y3 : y2);
#pragma unroll
            for (int dt = 0; dt < 8; dt++) {
                const uint32_t b0 = __float_as_uint(Vs[kp*8 + tig    ][dt*8 + gid]);
                const uint32_t b1 = __float_as_uint(Vs[kp*8 + tig + 4][dt*8 + gid]);
                mma_tf32_16x8x8(o[dt][0], o[dt][1], o[dt][2], o[dt][3],
                                a0, a1, a2, a3, b0, b1);
            }
        }
    }

    // ---- finalize: O /= l, write to [B,S,D] ----
    const float inv0 = 1.f / l0, inv1 = 1.f / l1;
    const int b = bh >> 4, h = bh & 15;
    float* ob0 = g_attn + (size_t)(b*SEQ + qg0)*DMODEL + h*DK;
    float* ob1 = g_attn + (size_t)(b*SEQ + qg1)*DMODEL + h*DK;
#pragma unroll
    for (int dt = 0; dt < 8; dt++) {
        const int d = dt*8 + 2*tig;
        *(float2*)(ob0 + d) = make_float2(o[dt][0]*inv0, o[dt][1]*inv0);
        *(float2*)(ob1 + d) = make_float2(o[dt][2]*inv1, o[dt][3]*inv1);
    }
}

// ---------------------------------------------------------------------------
// Launch.  Inputs: x, mask, w_qkv_w, w_qkv_b, w_o_w, w_o_b
// ---------------------------------------------------------------------------
extern "C" void kernel_launch(void* const* d_in, const int* in_sizes, int n_in,
                              void* d_out, int out_size)
{
    const float* x      = (const float*)d_in[0];
    const float* wqkv   = (const float*)d_in[2];
    const float* bqkv   = (const float*)d_in[3];
    const float* wo     = (const float*)d_in[4];
    const float* bo     = (const float*)d_in[5];
    float* out = (float*)d_out;

    float* attn_ptr;
    cudaGetSymbolAddress((void**)&attn_ptr, g_attn);

    // 1) QKV projection (tf32 mma.sync) -> g_q/g_k/g_v
    {
        dim3 grid(3*DMODEL/BN, M_TOK/BM);   // (24, 32)
        mma_gemm<<<grid, 256>>>(x, wqkv, bqkv, nullptr, M_TOK, 3*DMODEL, DMODEL, 0);
    }
    // 2) Causal flash attention (tf32 mma.sync) -> g_attn [B,S,D]
    {
        dim3 grid(SEQ/128, BATCH*NHEADS);   // (16, 32)
        flash_attn_mma<<<grid, 256>>>();
    }
    // 3) Output projection (tf32 mma.sync) -> d_out
    {
        dim3 grid(DMODEL/BN, M_TOK/BM);     // (8, 32)
        mma_gemm<<<grid, 256>>>(attn_ptr, wo, bo, out, M_TOK, DMODEL, DMODEL, 1);
    }
}

// round 8
// speedup vs baseline: 4.7442x; 1.2165x over previous
#include <cuda_runtime.h>
#include <cuda_bf16.h>
#include <cstdint>

// Problem constants
#define BATCH 2
#define SEQ   2048
#define DMODEL 1024
#define NHEADS 16
#define DK 64
#define M_TOK (BATCH*SEQ)          // 4096

// Scratch (no allocations allowed -> __device__ globals)
__device__ float g_q[BATCH*NHEADS*SEQ*DK];      // 16 MB
__device__ float g_k[BATCH*NHEADS*SEQ*DK];      // 16 MB
__device__ float g_v[BATCH*NHEADS*SEQ*DK];      // 16 MB
__device__ float g_attn[M_TOK*DMODEL];          // 16 MB

// ---------------------------------------------------------------------------
// helpers
// ---------------------------------------------------------------------------
__device__ __forceinline__ float to_tf32(float x) {
    uint32_t u;
    asm("cvt.rna.tf32.f32 %0, %1;" : "=r"(u) : "f"(x));
    return __uint_as_float(u);
}
__device__ __forceinline__ uint32_t to_tf32_u(float x) {
    uint32_t u;
    asm("cvt.rna.tf32.f32 %0, %1;" : "=r"(u) : "f"(x));
    return u;
}
__device__ __forceinline__ uint32_t smem_u32(const void* p) {
    uint32_t a;
    asm("{ .reg .u64 t; cvta.to.shared.u64 t, %1; cvt.u32.u64 %0, t; }"
        : "=r"(a) : "l"(p));
    return a;
}
__device__ __forceinline__ void cp_async16(uint32_t saddr, const void* gaddr) {
    asm volatile("cp.async.cg.shared.global [%0], [%1], 16;"
                 :: "r"(saddr), "l"(gaddr));
}
__device__ __forceinline__ void cp_commit() {
    asm volatile("cp.async.commit_group;");
}

__device__ __forceinline__ void mma_tf32_16x8x8(
    float& d0, float& d1, float& d2, float& d3,
    uint32_t a0, uint32_t a1, uint32_t a2, uint32_t a3,
    uint32_t b0, uint32_t b1)
{
    asm volatile(
        "mma.sync.aligned.m16n8k8.row.col.f32.tf32.tf32.f32 "
        "{%0,%1,%2,%3}, {%4,%5,%6,%7}, {%8,%9}, {%0,%1,%2,%3};"
        : "+f"(d0), "+f"(d1), "+f"(d2), "+f"(d3)
        : "r"(a0), "r"(a1), "r"(a2), "r"(a3), "r"(b0), "r"(b1));
}

#define SHFL(v, s)     __shfl_sync(0xffffffffu, v, s)
#define SHFL_XOR(v, m) __shfl_xor_sync(0xffffffffu, v, m)

// ===========================================================================
// tf32 tensor-core GEMM: C = A @ B^T + bias.  cp.async double-buffered.
// A: [M,K] row-major fp32, B: [N,K] row-major fp32. M,N % 128 == 0, K % 32 == 0.
// 128x128 tile, BK=32, 256 threads (8 warps, 2x4 warp grid, 64x32 per warp).
// smem: row-major [row][k] with stride 36 floats (fragment LDS bank = 4*gid+tig,
// conflict-free). tf32 rounding happens at fragment-load time.
// mode 0: scatter into g_q/g_k/g_v ([B,H,S,Dk]); mode 1: plain C write.
// ===========================================================================
#define BM 128
#define BN 128
#define BK2 32
#define ASTR 36                          // floats per smem row
#define OP_FLOATS (128*ASTR)             // 4608 floats per operand
#define STAGE_FLOATS (2*OP_FLOATS)       // A + B
#define GEMM_SMEM_BYTES (2*STAGE_FLOATS*4)   // 73728 B

__global__ __launch_bounds__(256)
void mma_gemm(const float* __restrict__ A, const float* __restrict__ B,
              const float* __restrict__ bias, float* __restrict__ C,
              int M, int N, int K, int mode)
{
    extern __shared__ float smx[];
    const uint32_t sbase = smem_u32(smx);

    const int tid = threadIdx.x;
    const int wid = tid >> 5;
    const int lane = tid & 31;
    const int gid = lane >> 2;
    const int tig = lane & 3;
    const int warpM = wid >> 2;
    const int warpN = wid & 3;
    const int bm = blockIdx.y, bn = blockIdx.x;

    const float* Abase = A + (size_t)(bm*BM)*K;
    const float* Bbase = B + (size_t)(bn*BN)*K;

    // copy indexing: 1024 float4 per operand, 4 per thread
    const int crow = (tid + 0*256) >> 3;     // rows tid>>3 .. with i*32 offset
    const int cq4  = tid & 7;

    float acc[4][4][4];
#pragma unroll
    for (int i = 0; i < 4; i++)
#pragma unroll
        for (int j = 0; j < 4; j++)
#pragma unroll
            for (int r = 0; r < 4; r++) acc[i][j][r] = 0.f;

    const int NC = K / BK2;

    // ---- stage copy: raw fp32, cp.async 16B ----
    auto copy_stage = [&](int c) {
        const int st = c & 1;
        const uint32_t abuf = sbase + (uint32_t)st*STAGE_FLOATS*4;
        const uint32_t bbuf = abuf + OP_FLOATS*4;
        const int k0 = c * BK2;
#pragma unroll
        for (int i = 0; i < 4; i++) {
            const int row = crow + i*32;
            const uint32_t soff = (uint32_t)(row*ASTR + cq4*4)*4;
            cp_async16(abuf + soff, Abase + (size_t)row*K + k0 + cq4*4);
            cp_async16(bbuf + soff, Bbase + (size_t)row*K + k0 + cq4*4);
        }
        cp_commit();
    };

    copy_stage(0);

    for (int c = 0; c < NC; c++) {
        if (c + 1 < NC) {
            copy_stage(c + 1);
            asm volatile("cp.async.wait_group 1;");
        } else {
            asm volatile("cp.async.wait_group 0;");
        }
        __syncthreads();

        const int st = c & 1;
        const float* As = smx + (size_t)st*STAGE_FLOATS;
        const float* Bs = As + OP_FLOATS;

#pragma unroll
        for (int ks = 0; ks < 4; ks++) {
            const int kb = ks*8;
            uint32_t bf[4][2];
#pragma unroll
            for (int nt = 0; nt < 4; nt++) {
                const int col = warpN*32 + nt*8 + gid;
                bf[nt][0] = to_tf32_u(Bs[col*ASTR + kb + tig    ]);
                bf[nt][1] = to_tf32_u(Bs[col*ASTR + kb + tig + 4]);
            }
#pragma unroll
            for (int mt = 0; mt < 4; mt++) {
                const int row = warpM*64 + mt*16 + gid;
                const uint32_t a0 = to_tf32_u(As[row*ASTR     + kb + tig    ]);
                const uint32_t a1 = to_tf32_u(As[(row+8)*ASTR + kb + tig    ]);
                const uint32_t a2 = to_tf32_u(As[row*ASTR     + kb + tig + 4]);
                const uint32_t a3 = to_tf32_u(As[(row+8)*ASTR + kb + tig + 4]);
#pragma unroll
                for (int nt = 0; nt < 4; nt++) {
                    mma_tf32_16x8x8(acc[mt][nt][0], acc[mt][nt][1],
                                    acc[mt][nt][2], acc[mt][nt][3],
                                    a0, a1, a2, a3, bf[nt][0], bf[nt][1]);
                }
            }
        }
        __syncthreads();
    }

    // ---- epilogue ----
#pragma unroll
    for (int mt = 0; mt < 4; mt++) {
        const int row0 = bm*BM + warpM*64 + mt*16 + gid;
#pragma unroll
        for (int nt = 0; nt < 4; nt++) {
            const int col = bn*BN + warpN*32 + nt*8 + tig*2;
            const float bz0 = bias[col], bz1 = bias[col+1];
#pragma unroll
            for (int half = 0; half < 2; half++) {
                const int row = row0 + half*8;
                float v0 = acc[mt][nt][half*2+0] + bz0;
                float v1 = acc[mt][nt][half*2+1] + bz1;
                if (mode == 1) {
                    *(float2*)(C + (size_t)row*N + col) = make_float2(v0, v1);
                } else {
                    const int sel = col >> 10;
                    const int d2  = col & 1023;
                    const int h   = d2 >> 6;
                    const int dk  = d2 & 63;
                    const int b   = row >> 11;
                    const int s   = row & 2047;
                    float* dst = (sel == 0) ? g_q : (sel == 1) ? g_k : g_v;
                    *(float2*)(dst + ((size_t)(((b<<4)+h)*SEQ + s))*DK + dk)
                        = make_float2(v0, v1);
                }
            }
        }
    }
}

// ===========================================================================
// Tensor-core causal flash attention (tf32 mma.sync) — unchanged from R6.
// ===========================================================================
__global__ __launch_bounds__(256, 2)
void flash_attn_mma()
{
    const int qt  = blockIdx.x;
    const int bh  = blockIdx.y;
    const int tid = threadIdx.x;
    const int w    = tid >> 5;
    const int lane = tid & 31;
    const int gid  = lane >> 2;
    const int tig  = lane & 3;

    __shared__ float Ks[64][68];
    __shared__ float Vs[64][72];

    const int r0  = w*16 + gid;
    const int qg0 = qt*128 + r0;
    const int qg1 = qg0 + 8;

    const float* qb = g_q + (size_t)(bh*SEQ + qt*128)*DK;
    uint32_t qa[8][4];
#pragma unroll
    for (int ks = 0; ks < 8; ks++) {
        qa[ks][0] = to_tf32_u(qb[(size_t)r0*DK     + ks*8 + tig    ] * 0.125f);
        qa[ks][1] = to_tf32_u(qb[(size_t)(r0+8)*DK + ks*8 + tig    ] * 0.125f);
        qa[ks][2] = to_tf32_u(qb[(size_t)r0*DK     + ks*8 + tig + 4] * 0.125f);
        qa[ks][3] = to_tf32_u(qb[(size_t)(r0+8)*DK + ks*8 + tig + 4] * 0.125f);
    }

    float o[8][4];
#pragma unroll
    for (int dt = 0; dt < 8; dt++)
#pragma unroll
        for (int r = 0; r < 4; r++) o[dt][r] = 0.f;
    float m0 = -1e30f, m1 = -1e30f, l0 = 0.f, l1 = 0.f;

    const int nkt = 2*qt + 2;
    const float* kb0 = g_k + (size_t)bh*SEQ*DK;
    const float* vb0 = g_v + (size_t)bh*SEQ*DK;

    for (int kt = 0; kt < nkt; kt++) {
        __syncthreads();
        {
            const float* kb = kb0 + (size_t)kt*64*DK;
            const float* vb = vb0 + (size_t)kt*64*DK;
#pragma unroll
            for (int i = 0; i < 4; i++) {
                const int f = tid + i*256;
                const int row = f >> 4;
                const int q4  = f & 15;
                float4 kv = *(const float4*)(kb + row*DK + q4*4);
                float4 vv = *(const float4*)(vb + row*DK + q4*4);
                float4 kt4, vt4;
                kt4.x = to_tf32(kv.x); kt4.y = to_tf32(kv.y);
                kt4.z = to_tf32(kv.z); kt4.w = to_tf32(kv.w);
                vt4.x = to_tf32(vv.x); vt4.y = to_tf32(vv.y);
                vt4.z = to_tf32(vv.z); vt4.w = to_tf32(vv.w);
                *(float4*)(&Ks[row][q4*4]) = kt4;
                *(float4*)(&Vs[row][q4*4]) = vt4;
            }
        }
        __syncthreads();

        float s[8][4];
#pragma unroll
        for (int nt = 0; nt < 8; nt++)
#pragma unroll
            for (int r = 0; r < 4; r++) s[nt][r] = 0.f;

#pragma unroll
        for (int ks = 0; ks < 8; ks++) {
#pragma unroll
            for (int nt = 0; nt < 8; nt++) {
                const uint32_t b0 = __float_as_uint(Ks[nt*8 + gid][ks*8 + tig    ]);
                const uint32_t b1 = __float_as_uint(Ks[nt*8 + gid][ks*8 + tig + 4]);
                mma_tf32_16x8x8(s[nt][0], s[nt][1], s[nt][2], s[nt][3],
                                qa[ks][0], qa[ks][1], qa[ks][2], qa[ks][3], b0, b1);
            }
        }

        if (kt >= 2*qt) {
#pragma unroll
            for (int nt = 0; nt < 8; nt++) {
                const int kg = kt*64 + nt*8 + 2*tig;
                if (kg     > qg0) s[nt][0] = -1e30f;
                if (kg + 1 > qg0) s[nt][1] = -1e30f;
                if (kg     > qg1) s[nt][2] = -1e30f;
                if (kg + 1 > qg1) s[nt][3] = -1e30f;
            }
        }

        float t0 = -1e30f, t1 = -1e30f;
#pragma unroll
        for (int nt = 0; nt < 8; nt++) {
            t0 = fmaxf(t0, fmaxf(s[nt][0], s[nt][1]));
            t1 = fmaxf(t1, fmaxf(s[nt][2], s[nt][3]));
        }
        t0 = fmaxf(t0, SHFL_XOR(t0, 1)); t0 = fmaxf(t0, SHFL_XOR(t0, 2));
        t1 = fmaxf(t1, SHFL_XOR(t1, 1)); t1 = fmaxf(t1, SHFL_XOR(t1, 2));
        const float m0n = fmaxf(m0, t0), m1n = fmaxf(m1, t1);
        const float c0 = __expf(m0 - m0n), c1 = __expf(m1 - m1n);
        m0 = m0n; m1 = m1n;

        float sum0 = 0.f, sum1 = 0.f;
#pragma unroll
        for (int nt = 0; nt < 8; nt++) {
            float p0 = __expf(s[nt][0] - m0);
            float p1 = __expf(s[nt][1] - m0);
            float p2 = __expf(s[nt][2] - m1);
            float p3 = __expf(s[nt][3] - m1);
            sum0 += p0 + p1; sum1 += p2 + p3;
            s[nt][0] = __uint_as_float(to_tf32_u(p0));
            s[nt][1] = __uint_as_float(to_tf32_u(p1));
            s[nt][2] = __uint_as_float(to_tf32_u(p2));
            s[nt][3] = __uint_as_float(to_tf32_u(p3));
        }
        sum0 += SHFL_XOR(sum0, 1); sum0 += SHFL_XOR(sum0, 2);
        sum1 += SHFL_XOR(sum1, 1); sum1 += SHFL_XOR(sum1, 2);
        l0 = l0*c0 + sum0;
        l1 = l1*c1 + sum1;
#pragma unroll
        for (int dt = 0; dt < 8; dt++) {
            o[dt][0] *= c0; o[dt][1] *= c0;
            o[dt][2] *= c1; o[dt][3] *= c1;
        }

        const int srcA = (lane & ~3) | (tig >> 1);
        const int srcB = srcA + 2;
        const bool odd = (tig & 1);
#pragma unroll
        for (int kp = 0; kp < 8; kp++) {
            const float x0 = SHFL(s[kp][0], srcA);
            const float x1 = SHFL(s[kp][1], srcA);
            const float x2 = SHFL(s[kp][2], srcA);
            const float x3 = SHFL(s[kp][3], srcA);
            const float y0 = SHFL(s[kp][0], srcB);
            const float y1 = SHFL(s[kp][1], srcB);
            const float y2 = SHFL(s[kp][2], srcB);
            const float y3 = SHFL(s[kp][3], srcB);
            const uint32_t a0 = __float_as_uint(odd ? x1 : x0);
            const uint32_t a1 = __float_as_uint(odd ? x3 : x2);
            const uint32_t a2 = __float_as_uint(odd ? y1 : y0);
            const uint32_t a3 = __float_as_uint(odd ? y3 : y2);
#pragma unroll
            for (int dt = 0; dt < 8; dt++) {
                const uint32_t b0 = __float_as_uint(Vs[kp*8 + tig    ][dt*8 + gid]);
                const uint32_t b1 = __float_as_uint(Vs[kp*8 + tig + 4][dt*8 + gid]);
                mma_tf32_16x8x8(o[dt][0], o[dt][1], o[dt][2], o[dt][3],
                                a0, a1, a2, a3, b0, b1);
            }
        }
    }

    const float inv0 = 1.f / l0, inv1 = 1.f / l1;
    const int b = bh >> 4, h = bh & 15;
    float* ob0 = g_attn + (size_t)(b*SEQ + qg0)*DMODEL + h*DK;
    float* ob1 = g_attn + (size_t)(b*SEQ + qg1)*DMODEL + h*DK;
#pragma unroll
    for (int dt = 0; dt < 8; dt++) {
        const int d = dt*8 + 2*tig;
        *(float2*)(ob0 + d) = make_float2(o[dt][0]*inv0, o[dt][1]*inv0);
        *(float2*)(ob1 + d) = make_float2(o[dt][2]*inv1, o[dt][3]*inv1);
    }
}

// ---------------------------------------------------------------------------
// Launch.  Inputs: x, mask, w_qkv_w, w_qkv_b, w_o_w, w_o_b
// ---------------------------------------------------------------------------
extern "C" void kernel_launch(void* const* d_in, const int* in_sizes, int n_in,
                              void* d_out, int out_size)
{
    const float* x      = (const float*)d_in[0];
    const float* wqkv   = (const float*)d_in[2];
    const float* bqkv   = (const float*)d_in[3];
    const float* wo     = (const float*)d_in[4];
    const float* bo     = (const float*)d_in[5];
    float* out = (float*)d_out;

    float* attn_ptr;
    cudaGetSymbolAddress((void**)&attn_ptr, g_attn);

    cudaFuncSetAttribute(mma_gemm, cudaFuncAttributeMaxDynamicSharedMemorySize,
                         GEMM_SMEM_BYTES);

    // 1) QKV projection (tf32 mma.sync, cp.async pipeline) -> g_q/g_k/g_v
    {
        dim3 grid(3*DMODEL/BN, M_TOK/BM);   // (24, 32)
        mma_gemm<<<grid, 256, GEMM_SMEM_BYTES>>>(x, wqkv, bqkv, nullptr,
                                                 M_TOK, 3*DMODEL, DMODEL, 0);
    }
    // 2) Causal flash attention (tf32 mma.sync) -> g_attn [B,S,D]
    {
        dim3 grid(SEQ/128, BATCH*NHEADS);   // (16, 32)
        flash_attn_mma<<<grid, 256>>>();
    }
    // 3) Output projection (tf32 mma.sync, cp.async pipeline) -> d_out
    {
        dim3 grid(DMODEL/BN, M_TOK/BM);     // (8, 32)
        mma_gemm<<<grid, 256, GEMM_SMEM_BYTES>>>(attn_ptr, wo, bo, out,
                                                 M_TOK, DMODEL, DMODEL, 1);
    }
}

// round 9
// speedup vs baseline: 5.3139x; 1.1201x over previous
#include <cuda_runtime.h>
#include <cuda_bf16.h>
#include <cstdint>

// Problem constants
#define BATCH 2
#define SEQ   2048
#define DMODEL 1024
#define NHEADS 16
#define DK 64
#define M_TOK (BATCH*SEQ)          // 4096

// Scratch (no allocations allowed -> __device__ globals)
__device__ float g_q[BATCH*NHEADS*SEQ*DK];      // 16 MB (tf32-rounded)
__device__ float g_k[BATCH*NHEADS*SEQ*DK];      // 16 MB (tf32-rounded)
__device__ float g_v[BATCH*NHEADS*SEQ*DK];      // 16 MB (tf32-rounded)
__device__ float g_attn[M_TOK*DMODEL];          // 16 MB (tf32-rounded)
__device__ float g_x[M_TOK*DMODEL];             // 16 MB (tf32-rounded x)
__device__ float g_wqkv[3*DMODEL*DMODEL];       // 12 MB (tf32-rounded)
__device__ float g_wo[DMODEL*DMODEL];           //  4 MB (tf32-rounded)

// ---------------------------------------------------------------------------
// helpers
// ---------------------------------------------------------------------------
__device__ __forceinline__ float to_tf32(float x) {
    uint32_t u;
    asm("cvt.rna.tf32.f32 %0, %1;" : "=r"(u) : "f"(x));
    return __uint_as_float(u);
}
__device__ __forceinline__ uint32_t to_tf32_u(float x) {
    uint32_t u;
    asm("cvt.rna.tf32.f32 %0, %1;" : "=r"(u) : "f"(x));
    return u;
}
__device__ __forceinline__ uint32_t smem_u32(const void* p) {
    uint32_t a;
    asm("{ .reg .u64 t; cvta.to.shared.u64 t, %1; cvt.u32.u64 %0, t; }"
        : "=r"(a) : "l"(p));
    return a;
}
__device__ __forceinline__ void cp_async16(uint32_t saddr, const void* gaddr) {
    asm volatile("cp.async.cg.shared.global [%0], [%1], 16;"
                 :: "r"(saddr), "l"(gaddr));
}
__device__ __forceinline__ void cp_commit() {
    asm volatile("cp.async.commit_group;");
}
__device__ __forceinline__ void ldsm_x4(uint32_t& r0, uint32_t& r1,
                                        uint32_t& r2, uint32_t& r3, uint32_t addr) {
    asm volatile("ldmatrix.sync.aligned.m8n8.x4.shared.b16 {%0,%1,%2,%3}, [%4];"
                 : "=r"(r0), "=r"(r1), "=r"(r2), "=r"(r3) : "r"(addr));
}

__device__ __forceinline__ void mma_tf32_16x8x8(
    float& d0, float& d1, float& d2, float& d3,
    uint32_t a0, uint32_t a1, uint32_t a2, uint32_t a3,
    uint32_t b0, uint32_t b1)
{
    asm volatile(
        "mma.sync.aligned.m16n8k8.row.col.f32.tf32.tf32.f32 "
        "{%0,%1,%2,%3}, {%4,%5,%6,%7}, {%8,%9}, {%0,%1,%2,%3};"
        : "+f"(d0), "+f"(d1), "+f"(d2), "+f"(d3)
        : "r"(a0), "r"(a1), "r"(a2), "r"(a3), "r"(b0), "r"(b1));
}

#define SHFL(v, s)     __shfl_sync(0xffffffffu, v, s)
#define SHFL_XOR(v, m) __shfl_xor_sync(0xffffffffu, v, m)

// ---------------------------------------------------------------------------
// Pre-pass: tf32-round a float array (float4 grid-stride).
// ---------------------------------------------------------------------------
__global__ __launch_bounds__(256)
void roundcopy(const float4* __restrict__ src, float4* __restrict__ dst, int n4)
{
    for (int i = blockIdx.x*blockDim.x + threadIdx.x; i < n4;
         i += gridDim.x*blockDim.x) {
        float4 v = src[i];
        v.x = to_tf32(v.x); v.y = to_tf32(v.y);
        v.z = to_tf32(v.z); v.w = to_tf32(v.w);
        dst[i] = v;
    }
}

// ===========================================================================
// tf32 tensor-core GEMM: C = A @ B^T + bias.  cp.async double-buffered,
// ldmatrix fragment loads, inputs pre-rounded to tf32.
// A: [M,K] row-major, B: [N,K] row-major. M,N % 128 == 0, K % 32 == 0.
// 128x128 tile, BK=32, 256 threads (8 warps, 2x4 warp grid, 64x32 per warp).
// smem row-major stride 36 floats (ldmatrix row-banks conflict-free).
// mode 0: scatter tf32-rounded into g_q/g_k/g_v; mode 1: plain fp32 C write.
// ===========================================================================
#define BM 128
#define BN 128
#define BK2 32
#define ASTR 36
#define OP_FLOATS (128*ASTR)
#define STAGE_FLOATS (2*OP_FLOATS)
#define GEMM_SMEM_BYTES (2*STAGE_FLOATS*4)   // 73728 B

__global__ __launch_bounds__(256)
void mma_gemm(const float* __restrict__ A, const float* __restrict__ B,
              const float* __restrict__ bias, float* __restrict__ C,
              int M, int N, int K, int mode)
{
    extern __shared__ float smx[];
    const uint32_t sbase = smem_u32(smx);

    const int tid = threadIdx.x;
    const int wid = tid >> 5;
    const int lane = tid & 31;
    const int gid = lane >> 2;
    const int tig = lane & 3;
    const int warpM = wid >> 2;
    const int warpN = wid & 3;
    const int bm = blockIdx.y, bn = blockIdx.x;

    const float* Abase = A + (size_t)(bm*BM)*K;
    const float* Bbase = B + (size_t)(bn*BN)*K;

    const int crow = tid >> 3;
    const int cq4  = tid & 7;

    // ldmatrix per-lane address components
    const int a_row  = (lane & 7) + ((lane >> 3) & 1)*8;   // 0..15
    const int a_kofs = (lane >> 4)*4;
    const int b_row  = (lane >> 4)*8 + (lane & 7);         // 0..15
    const int b_kofs = ((lane >> 3) & 1)*4;

    float acc[4][4][4];
#pragma unroll
    for (int i = 0; i < 4; i++)
#pragma unroll
        for (int j = 0; j < 4; j++)
#pragma unroll
            for (int r = 0; r < 4; r++) acc[i][j][r] = 0.f;

    const int NC = K / BK2;

    auto copy_stage = [&](int c) {
        const int st = c & 1;
        const uint32_t abuf = sbase + (uint32_t)st*STAGE_FLOATS*4;
        const uint32_t bbuf = abuf + OP_FLOATS*4;
        const int k0 = c * BK2;
#pragma unroll
        for (int i = 0; i < 4; i++) {
            const int row = crow + i*32;
            const uint32_t soff = (uint32_t)(row*ASTR + cq4*4)*4;
            cp_async16(abuf + soff, Abase + (size_t)row*K + k0 + cq4*4);
            cp_async16(bbuf + soff, Bbase + (size_t)row*K + k0 + cq4*4);
        }
        cp_commit();
    };

    copy_stage(0);

    for (int c = 0; c < NC; c++) {
        if (c + 1 < NC) {
            copy_stage(c + 1);
            asm volatile("cp.async.wait_group 1;");
        } else {
            asm volatile("cp.async.wait_group 0;");
        }
        __syncthreads();

        const int st = c & 1;
        const uint32_t stage_base = sbase + (uint32_t)st*STAGE_FLOATS*4;
        const uint32_t aAddr = stage_base
            + (uint32_t)((warpM*64 + a_row)*ASTR + a_kofs)*4;
        const uint32_t bAddr = stage_base + OP_FLOATS*4
            + (uint32_t)((warpN*32 + b_row)*ASTR + b_kofs)*4;

#pragma unroll
        for (int ks = 0; ks < 4; ks++) {
            const uint32_t ko = ks*32;      // ks*8 floats * 4B
            uint32_t bf[4][2];
            ldsm_x4(bf[0][0], bf[0][1], bf[1][0], bf[1][1], bAddr + ko);
            ldsm_x4(bf[2][0], bf[2][1], bf[3][0], bf[3][1],
                    bAddr + 16*ASTR*4 + ko);
#pragma unroll
            for (int mt = 0; mt < 4; mt++) {
                uint32_t a0, a1, a2, a3;
                ldsm_x4(a0, a1, a2, a3, aAddr + (uint32_t)mt*16*ASTR*4 + ko);
#pragma unroll
                for (int nt = 0; nt < 4; nt++) {
                    mma_tf32_16x8x8(acc[mt][nt][0], acc[mt][nt][1],
                                    acc[mt][nt][2], acc[mt][nt][3],
                                    a0, a1, a2, a3, bf[nt][0], bf[nt][1]);
                }
            }
        }
        __syncthreads();
    }

    // ---- epilogue ----
#pragma unroll
    for (int mt = 0; mt < 4; mt++) {
        const int row0 = bm*BM + warpM*64 + mt*16 + gid;
#pragma unroll
        for (int nt = 0; nt < 4; nt++) {
            const int col = bn*BN + warpN*32 + nt*8 + tig*2;
            const float bz0 = bias[col], bz1 = bias[col+1];
#pragma unroll
            for (int half = 0; half < 2; half++) {
                const int row = row0 + half*8;
                float v0 = acc[mt][nt][half*2+0] + bz0;
                float v1 = acc[mt][nt][half*2+1] + bz1;
                if (mode == 1) {
                    *(float2*)(C + (size_t)row*N + col) = make_float2(v0, v1);
                } else {
                    v0 = to_tf32(v0); v1 = to_tf32(v1);   // pre-round for attn
                    const int sel = col >> 10;
                    const int d2  = col & 1023;
                    const int h   = d2 >> 6;
                    const int dk  = d2 & 63;
                    const int b   = row >> 11;
                    const int s   = row & 2047;
                    float* dst = (sel == 0) ? g_q : (sel == 1) ? g_k : g_v;
                    *(float2*)(dst + ((size_t)(((b<<4)+h)*SEQ + s))*DK + dk)
                        = make_float2(v0, v1);
                }
            }
        }
    }
}

// ===========================================================================
// Tensor-core causal flash attention (tf32 mma.sync).
// Inputs g_q/g_k/g_v pre-rounded to tf32. cp.async double-buffered K/V tiles,
// ldmatrix K fragments. Output tf32-rounded into g_attn.
// Per stage: K 64x64 (stride 68) + V 64x64 (stride 72) = 8960 floats.
// ===========================================================================
#define AT_KSTR 68
#define AT_VSTR 72
#define AT_STAGE_FLOATS (64*AT_KSTR + 64*AT_VSTR)     // 8960
#define AT_SMEM_BYTES (2*AT_STAGE_FLOATS*4)           // 71680

__global__ __launch_bounds__(256, 2)
void flash_attn_mma()
{
    extern __shared__ float atm[];
    const uint32_t sbase = smem_u32(atm);

    const int qt  = blockIdx.x;
    const int bh  = blockIdx.y;
    const int tid = threadIdx.x;
    const int w    = tid >> 5;
    const int lane = tid & 31;
    const int gid  = lane >> 2;
    const int tig  = lane & 3;

    const int r0  = w*16 + gid;
    const int qg0 = qt*128 + r0;
    const int qg1 = qg0 + 8;

    // ldmatrix per-lane address components for K fragments
    const int k_row  = (lane >> 4)*8 + (lane & 7);   // within 16-key pair block
    const int k_kofs = ((lane >> 3) & 1)*4;

    // Q fragments (pre-rounded; *0.125 is exponent-only, stays tf32-exact)
    const float* qb = g_q + (size_t)(bh*SEQ + qt*128)*DK;
    uint32_t qa[8][4];
#pragma unroll
    for (int ks = 0; ks < 8; ks++) {
        qa[ks][0] = __float_as_uint(qb[(size_t)r0*DK     + ks*8 + tig    ] * 0.125f);
        qa[ks][1] = __float_as_uint(qb[(size_t)(r0+8)*DK + ks*8 + tig    ] * 0.125f);
        qa[ks][2] = __float_as_uint(qb[(size_t)r0*DK     + ks*8 + tig + 4] * 0.125f);
        qa[ks][3] = __float_as_uint(qb[(size_t)(r0+8)*DK + ks*8 + tig + 4] * 0.125f);
    }

    float o[8][4];
#pragma unroll
    for (int dt = 0; dt < 8; dt++)
#pragma unroll
        for (int r = 0; r < 4; r++) o[dt][r] = 0.f;
    float m0 = -1e30f, m1 = -1e30f, l0 = 0.f, l1 = 0.f;

    const int nkt = 2*qt + 2;
    const float* kb0 = g_k + (size_t)bh*SEQ*DK;
    const float* vb0 = g_v + (size_t)bh*SEQ*DK;

    auto copy_kv = [&](int kt, int stage) {
        const uint32_t kbuf = sbase + (uint32_t)stage*AT_STAGE_FLOATS*4;
        const uint32_t vbuf = kbuf + 64*AT_KSTR*4;
        const float* kb = kb0 + (size_t)kt*64*DK;
        const float* vb = vb0 + (size_t)kt*64*DK;
#pragma unroll
        for (int i = 0; i < 4; i++) {
            const int f = tid + i*256;
            const int row = f >> 4;
            const int q4  = f & 15;
            cp_async16(kbuf + (uint32_t)(row*AT_KSTR + q4*4)*4, kb + row*DK + q4*4);
            cp_async16(vbuf + (uint32_t)(row*AT_VSTR + q4*4)*4, vb + row*DK + q4*4);
        }
        cp_commit();
    };

    copy_kv(0, 0);

    for (int kt = 0; kt < nkt; kt++) {
        __syncthreads();              // all warps done with buf[(kt+1)&1]
        if (kt + 1 < nkt) {
            copy_kv(kt + 1, (kt + 1) & 1);
            asm volatile("cp.async.wait_group 1;");
        } else {
            asm volatile("cp.async.wait_group 0;");
        }
        __syncthreads();

        const int st = kt & 1;
        const uint32_t kbase = sbase + (uint32_t)st*AT_STAGE_FLOATS*4;
        const float* Vs = atm + (size_t)st*AT_STAGE_FLOATS + 64*AT_KSTR;

        // ---- S = Q K^T ----
        float s[8][4];
#pragma unroll
        for (int nt = 0; nt < 8; nt++)
#pragma unroll
            for (int r = 0; r < 4; r++) s[nt][r] = 0.f;

        const uint32_t kAddr = kbase + (uint32_t)(k_row*AT_KSTR + k_kofs)*4;
#pragma unroll
        for (int ks = 0; ks < 8; ks++) {
            const uint32_t ko = ks*32;
#pragma unroll
            for (int pair = 0; pair < 4; pair++) {
                uint32_t b00, b01, b10, b11;
                ldsm_x4(b00, b01, b10, b11,
                        kAddr + (uint32_t)pair*16*AT_KSTR*4 + ko);
                mma_tf32_16x8x8(s[2*pair][0], s[2*pair][1],
                                s[2*pair][2], s[2*pair][3],
                                qa[ks][0], qa[ks][1], qa[ks][2], qa[ks][3],
                                b00, b01);
                mma_tf32_16x8x8(s[2*pair+1][0], s[2*pair+1][1],
                                s[2*pair+1][2], s[2*pair+1][3],
                                qa[ks][0], qa[ks][1], qa[ks][2], qa[ks][3],
                                b10, b11);
            }
        }

        // ---- causal mask ----
        if (kt >= 2*qt) {
#pragma unroll
            for (int nt = 0; nt < 8; nt++) {
                const int kg = kt*64 + nt*8 + 2*tig;
                if (kg     > qg0) s[nt][0] = -1e30f;
                if (kg + 1 > qg0) s[nt][1] = -1e30f;
                if (kg     > qg1) s[nt][2] = -1e30f;
                if (kg + 1 > qg1) s[nt][3] = -1e30f;
            }
        }

        // ---- online softmax ----
        float t0 = -1e30f, t1 = -1e30f;
#pragma unroll
        for (int nt = 0; nt < 8; nt++) {
            t0 = fmaxf(t0, fmaxf(s[nt][0], s[nt][1]));
            t1 = fmaxf(t1, fmaxf(s[nt][2], s[nt][3]));
        }
        t0 = fmaxf(t0, SHFL_XOR(t0, 1)); t0 = fmaxf(t0, SHFL_XOR(t0, 2));
        t1 = fmaxf(t1, SHFL_XOR(t1, 1)); t1 = fmaxf(t1, SHFL_XOR(t1, 2));
        const float m0n = fmaxf(m0, t0), m1n = fmaxf(m1, t1);
        const float c0 = __expf(m0 - m0n), c1 = __expf(m1 - m1n);
        m0 = m0n; m1 = m1n;

        float sum0 = 0.f, sum1 = 0.f;
#pragma unroll
        for (int nt = 0; nt < 8; nt++) {
            float p0 = __expf(s[nt][0] - m0);
            float p1 = __expf(s[nt][1] - m0);
            float p2 = __expf(s[nt][2] - m1);
            float p3 = __expf(s[nt][3] - m1);
            sum0 += p0 + p1; sum1 += p2 + p3;
            s[nt][0] = __uint_as_float(to_tf32_u(p0));
            s[nt][1] = __uint_as_float(to_tf32_u(p1));
            s[nt][2] = __uint_as_float(to_tf32_u(p2));
            s[nt][3] = __uint_as_float(to_tf32_u(p3));
        }
        sum0 += SHFL_XOR(sum0, 1); sum0 += SHFL_XOR(sum0, 2);
        sum1 += SHFL_XOR(sum1, 1); sum1 += SHFL_XOR(sum1, 2);
        l0 = l0*c0 + sum0;
        l1 = l1*c1 + sum1;
#pragma unroll
        for (int dt = 0; dt < 8; dt++) {
            o[dt][0] *= c0; o[dt][1] *= c0;
            o[dt][2] *= c1; o[dt][3] *= c1;
        }

        // ---- O += P V (quad-shuffle P -> A-fragments) ----
        const int srcA = (lane & ~3) | (tig >> 1);
        const int srcB = srcA + 2;
        const bool odd = (tig & 1);
#pragma unroll
        for (int kp = 0; kp < 8; kp++) {
            const float x0 = SHFL(s[kp][0], srcA);
            const float x1 = SHFL(s[kp][1], srcA);
            const float x2 = SHFL(s[kp][2], srcA);
            const float x3 = SHFL(s[kp][3], srcA);
            const float y0 = SHFL(s[kp][0], srcB);
            const float y1 = SHFL(s[kp][1], srcB);
            const float y2 = SHFL(s[kp][2], srcB);
            const float y3 = SHFL(s[kp][3], srcB);
            const uint32_t a0 = __float_as_uint(odd ? x1 : x0);
            const uint32_t a1 = __float_as_uint(odd ? x3 : x2);
            const uint32_t a2 = __float_as_uint(odd ? y1 : y0);
            const uint32_t a3 = __float_as_uint(odd ? y3 : y2);
#pragma unroll
            for (int dt = 0; dt < 8; dt++) {
                const uint32_t b0 =
                    __float_as_uint(Vs[(kp*8 + tig    )*AT_VSTR + dt*8 + gid]);
                const uint32_t b1 =
                    __float_as_uint(Vs[(kp*8 + tig + 4)*AT_VSTR + dt*8 + gid]);
                mma_tf32_16x8x8(o[dt][0], o[dt][1], o[dt][2], o[dt][3],
                                a0, a1, a2, a3, b0, b1);
            }
        }
    }

    // ---- finalize: O /= l, tf32-round (O-proj input), write [B,S,D] ----
    const float inv0 = 1.f / l0, inv1 = 1.f / l1;
    const int b = bh >> 4, h = bh & 15;
    float* ob0 = g_attn + (size_t)(b*SEQ + qg0)*DMODEL + h*DK;
    float* ob1 = g_attn + (size_t)(b*SEQ + qg1)*DMODEL + h*DK;
#pragma unroll
    for (int dt = 0; dt < 8; dt++) {
        const int d = dt*8 + 2*tig;
        *(float2*)(ob0 + d) = make_float2(to_tf32(o[dt][0]*inv0),
                                          to_tf32(o[dt][1]*inv0));
        *(float2*)(ob1 + d) = make_float2(to_tf32(o[dt][2]*inv1),
                                          to_tf32(o[dt][3]*inv1));
    }
}

// ---------------------------------------------------------------------------
// Launch.  Inputs: x, mask, w_qkv_w, w_qkv_b, w_o_w, w_o_b
// ---------------------------------------------------------------------------
extern "C" void kernel_launch(void* const* d_in, const int* in_sizes, int n_in,
                              void* d_out, int out_size)
{
    const float* x      = (const float*)d_in[0];
    const float* wqkv   = (const float*)d_in[2];
    const float* bqkv   = (const float*)d_in[3];
    const float* wo     = (const float*)d_in[4];
    const float* bo     = (const float*)d_in[5];
    float* out = (float*)d_out;

    float *p_attn, *p_x, *p_wqkv, *p_wo;
    cudaGetSymbolAddress((void**)&p_attn, g_attn);
    cudaGetSymbolAddress((void**)&p_x,    g_x);
    cudaGetSymbolAddress((void**)&p_wqkv, g_wqkv);
    cudaGetSymbolAddress((void**)&p_wo,   g_wo);

    cudaFuncSetAttribute(mma_gemm, cudaFuncAttributeMaxDynamicSharedMemorySize,
                         GEMM_SMEM_BYTES);
    cudaFuncSetAttribute(flash_attn_mma,
                         cudaFuncAttributeMaxDynamicSharedMemorySize,
                         AT_SMEM_BYTES);

    // 0) pre-round inputs/weights to tf32
    roundcopy<<<2048, 256>>>((const float4*)x,    (float4*)p_x,    M_TOK*DMODEL/4);
    roundcopy<<<2048, 256>>>((const float4*)wqkv, (float4*)p_wqkv, 3*DMODEL*DMODEL/4);
    roundcopy<<<1024, 256>>>((const float4*)wo,   (float4*)p_wo,   DMODEL*DMODEL/4);

    // 1) QKV projection -> g_q/g_k/g_v (tf32-rounded at write)
    {
        dim3 grid(3*DMODEL/BN, M_TOK/BM);   // (24, 32)
        mma_gemm<<<grid, 256, GEMM_SMEM_BYTES>>>(p_x, p_wqkv, bqkv, nullptr,
                                                 M_TOK, 3*DMODEL, DMODEL, 0);
    }
    // 2) Causal flash attention -> g_attn (tf32-rounded at write)
    {
        dim3 grid(SEQ/128, BATCH*NHEADS);   // (16, 32)
        flash_attn_mma<<<grid, 256, AT_SMEM_BYTES>>>();
    }
    // 3) Output projection -> d_out (full fp32 epilogue)
    {
        dim3 grid(DMODEL/BN, M_TOK/BM);     // (8, 32)
        mma_gemm<<<grid, 256, GEMM_SMEM_BYTES>>>(p_attn, p_wo, bo, out,
                                                 M_TOK, DMODEL, DMODEL, 1);
    }
}

// round 10
// speedup vs baseline: 5.3563x; 1.0080x over previous
#include <cuda_runtime.h>
#include <cuda_bf16.h>
#include <cstdint>

// Problem constants
#define BATCH 2
#define SEQ   2048
#define DMODEL 1024
#define NHEADS 16
#define DK 64
#define M_TOK (BATCH*SEQ)          // 4096

// Scratch (no allocations allowed -> __device__ globals)
__device__ float g_q[BATCH*NHEADS*SEQ*DK];      // 16 MB (tf32-rounded)
__device__ float g_k[BATCH*NHEADS*SEQ*DK];      // 16 MB (tf32-rounded)
__device__ float g_v[BATCH*NHEADS*SEQ*DK];      // 16 MB (tf32-rounded)
__device__ float g_attn[M_TOK*DMODEL];          // 16 MB (tf32-rounded)
__device__ float g_x[M_TOK*DMODEL];             // 16 MB (tf32-rounded x)
__device__ float g_wqkv[3*DMODEL*DMODEL];       // 12 MB (tf32-rounded)
__device__ float g_wo[DMODEL*DMODEL];           //  4 MB (tf32-rounded)

// ---------------------------------------------------------------------------
// helpers
// ---------------------------------------------------------------------------
__device__ __forceinline__ float to_tf32(float x) {
    uint32_t u;
    asm("cvt.rna.tf32.f32 %0, %1;" : "=r"(u) : "f"(x));
    return __uint_as_float(u);
}
__device__ __forceinline__ uint32_t to_tf32_u(float x) {
    uint32_t u;
    asm("cvt.rna.tf32.f32 %0, %1;" : "=r"(u) : "f"(x));
    return u;
}
__device__ __forceinline__ uint32_t smem_u32(const void* p) {
    uint32_t a;
    asm("{ .reg .u64 t; cvta.to.shared.u64 t, %1; cvt.u32.u64 %0, t; }"
        : "=r"(a) : "l"(p));
    return a;
}
__device__ __forceinline__ void cp_async16(uint32_t saddr, const void* gaddr) {
    asm volatile("cp.async.cg.shared.global [%0], [%1], 16;"
                 :: "r"(saddr), "l"(gaddr));
}
__device__ __forceinline__ void cp_commit() {
    asm volatile("cp.async.commit_group;");
}
__device__ __forceinline__ void ldsm_x4(uint32_t& r0, uint32_t& r1,
                                        uint32_t& r2, uint32_t& r3, uint32_t addr) {
    asm volatile("ldmatrix.sync.aligned.m8n8.x4.shared.b16 {%0,%1,%2,%3}, [%4];"
                 : "=r"(r0), "=r"(r1), "=r"(r2), "=r"(r3) : "r"(addr));
}

__device__ __forceinline__ void mma_tf32_16x8x8(
    float& d0, float& d1, float& d2, float& d3,
    uint32_t a0, uint32_t a1, uint32_t a2, uint32_t a3,
    uint32_t b0, uint32_t b1)
{
    asm volatile(
        "mma.sync.aligned.m16n8k8.row.col.f32.tf32.tf32.f32 "
        "{%0,%1,%2,%3}, {%4,%5,%6,%7}, {%8,%9}, {%0,%1,%2,%3};"
        : "+f"(d0), "+f"(d1), "+f"(d2), "+f"(d3)
        : "r"(a0), "r"(a1), "r"(a2), "r"(a3), "r"(b0), "r"(b1));
}

#define SHFL(v, s)     __shfl_sync(0xffffffffu, v, s)
#define SHFL_XOR(v, m) __shfl_xor_sync(0xffffffffu, v, m)

// ---------------------------------------------------------------------------
// Pre-pass: tf32-round a float array (float4 grid-stride).
// ---------------------------------------------------------------------------
__global__ __launch_bounds__(256)
void roundcopy(const float4* __restrict__ src, float4* __restrict__ dst, int n4)
{
    for (int i = blockIdx.x*blockDim.x + threadIdx.x; i < n4;
         i += gridDim.x*blockDim.x) {
        float4 v = src[i];
        v.x = to_tf32(v.x); v.y = to_tf32(v.y);
        v.z = to_tf32(v.z); v.w = to_tf32(v.w);
        dst[i] = v;
    }
}

// ===========================================================================
// tf32 tensor-core GEMM: C = A @ B^T + bias.  3-stage cp.async pipeline,
// one __syncthreads per BK-chunk, ldmatrix fragment loads, tf32 inputs.
// A: [M,K] row-major, B: [N,K] row-major. M,N % 128 == 0, K % 32 == 0 (>=64).
// 128x128 tile, BK=32, 256 threads (8 warps, 2x4 warp grid, 64x32 per warp).
// mode 0: scatter tf32-rounded into g_q/g_k/g_v; mode 1: plain fp32 C write.
// ===========================================================================
#define BM 128
#define BN 128
#define BK2 32
#define ASTR 36
#define OP_FLOATS (128*ASTR)
#define STAGE_FLOATS (2*OP_FLOATS)
#define NSTAGE 3
#define GEMM_SMEM_BYTES (NSTAGE*STAGE_FLOATS*4)   // 110592 B

__global__ __launch_bounds__(256)
void mma_gemm(const float* __restrict__ A, const float* __restrict__ B,
              const float* __restrict__ bias, float* __restrict__ C,
              int M, int N, int K, int mode)
{
    extern __shared__ float smx[];
    const uint32_t sbase = smem_u32(smx);

    const int tid = threadIdx.x;
    const int wid = tid >> 5;
    const int lane = tid & 31;
    const int gid = lane >> 2;
    const int tig = lane & 3;
    const int warpM = wid >> 2;
    const int warpN = wid & 3;
    const int bm = blockIdx.y, bn = blockIdx.x;

    const float* Abase = A + (size_t)(bm*BM)*K;
    const float* Bbase = B + (size_t)(bn*BN)*K;

    const int crow = tid >> 3;
    const int cq4  = tid & 7;

    const int a_row  = (lane & 7) + ((lane >> 3) & 1)*8;
    const int a_kofs = (lane >> 4)*4;
    const int b_row  = (lane >> 4)*8 + (lane & 7);
    const int b_kofs = ((lane >> 3) & 1)*4;

    float acc[4][4][4];
#pragma unroll
    for (int i = 0; i < 4; i++)
#pragma unroll
        for (int j = 0; j < 4; j++)
#pragma unroll
            for (int r = 0; r < 4; r++) acc[i][j][r] = 0.f;

    const int NC = K / BK2;

    auto copy_stage = [&](int c, int st) {
        const uint32_t abuf = sbase + (uint32_t)st*STAGE_FLOATS*4;
        const uint32_t bbuf = abuf + OP_FLOATS*4;
        const int k0 = c * BK2;
#pragma unroll
        for (int i = 0; i < 4; i++) {
            const int row = crow + i*32;
            const uint32_t soff = (uint32_t)(row*ASTR + cq4*4)*4;
            cp_async16(abuf + soff, Abase + (size_t)row*K + k0 + cq4*4);
            cp_async16(bbuf + soff, Bbase + (size_t)row*K + k0 + cq4*4);
        }
        cp_commit();
    };

    copy_stage(0, 0);
    copy_stage(1, 1);

    int cs = 0;                 // compute stage
    for (int c = 0; c < NC; c++) {
        if (c + 1 < NC) {
            asm volatile("cp.async.wait_group 1;");
        } else {
            asm volatile("cp.async.wait_group 0;");
        }
        __syncthreads();        // stage cs ready for ALL; stage (cs+2)%3 free

        if (c + 2 < NC) {
            int ps = cs + 2; if (ps >= NSTAGE) ps -= NSTAGE;
            copy_stage(c + 2, ps);
        }

        const uint32_t stage_base = sbase + (uint32_t)cs*STAGE_FLOATS*4;
        const uint32_t aAddr = stage_base
            + (uint32_t)((warpM*64 + a_row)*ASTR + a_kofs)*4;
        const uint32_t bAddr = stage_base + OP_FLOATS*4
            + (uint32_t)((warpN*32 + b_row)*ASTR + b_kofs)*4;

#pragma unroll
        for (int ks = 0; ks < 4; ks++) {
            const uint32_t ko = ks*32;
            uint32_t bf[4][2];
            ldsm_x4(bf[0][0], bf[0][1], bf[1][0], bf[1][1], bAddr + ko);
            ldsm_x4(bf[2][0], bf[2][1], bf[3][0], bf[3][1],
                    bAddr + 16*ASTR*4 + ko);
#pragma unroll
            for (int mt = 0; mt < 4; mt++) {
                uint32_t a0, a1, a2, a3;
                ldsm_x4(a0, a1, a2, a3, aAddr + (uint32_t)mt*16*ASTR*4 + ko);
#pragma unroll
                for (int nt = 0; nt < 4; nt++) {
                    mma_tf32_16x8x8(acc[mt][nt][0], acc[mt][nt][1],
                                    acc[mt][nt][2], acc[mt][nt][3],
                                    a0, a1, a2, a3, bf[nt][0], bf[nt][1]);
                }
            }
        }
        cs = cs + 1; if (cs >= NSTAGE) cs -= NSTAGE;
    }

    // ---- epilogue ----
#pragma unroll
    for (int mt = 0; mt < 4; mt++) {
        const int row0 = bm*BM + warpM*64 + mt*16 + gid;
#pragma unroll
        for (int nt = 0; nt < 4; nt++) {
            const int col = bn*BN + warpN*32 + nt*8 + tig*2;
            const float bz0 = bias[col], bz1 = bias[col+1];
#pragma unroll
            for (int half = 0; half < 2; half++) {
                const int row = row0 + half*8;
                float v0 = acc[mt][nt][half*2+0] + bz0;
                float v1 = acc[mt][nt][half*2+1] + bz1;
                if (mode == 1) {
                    *(float2*)(C + (size_t)row*N + col) = make_float2(v0, v1);
                } else {
                    v0 = to_tf32(v0); v1 = to_tf32(v1);
                    const int sel = col >> 10;
                    const int d2  = col & 1023;
                    const int h   = d2 >> 6;
                    const int dk  = d2 & 63;
                    const int b   = row >> 11;
                    const int s   = row & 2047;
                    float* dst = (sel == 0) ? g_q : (sel == 1) ? g_k : g_v;
                    *(float2*)(dst + ((size_t)(((b<<4)+h)*SEQ + s))*DK + dk)
                        = make_float2(v0, v1);
                }
            }
        }
    }
}

// ===========================================================================
// Tensor-core causal flash attention (tf32 mma.sync).
// 3-stage cp.async K/V pipeline, one __syncthreads per K-tile, ldmatrix K
// fragments. Heaviest q-tiles scheduled first (qt = 15 - blockIdx.x).
// Per stage: K 64x64 (stride 68) + V 64x64 (stride 72) = 8960 floats.
// ===========================================================================
#define AT_KSTR 68
#define AT_VSTR 72
#define AT_STAGE_FLOATS (64*AT_KSTR + 64*AT_VSTR)     // 8960
#define AT_NSTAGE 3
#define AT_SMEM_BYTES (AT_NSTAGE*AT_STAGE_FLOATS*4)   // 107520

__global__ __launch_bounds__(256, 2)
void flash_attn_mma()
{
    extern __shared__ float atm[];
    const uint32_t sbase = smem_u32(atm);

    const int qt  = (int)gridDim.x - 1 - (int)blockIdx.x;   // heavy tiles first
    const int bh  = blockIdx.y;
    const int tid = threadIdx.x;
    const int w    = tid >> 5;
    const int lane = tid & 31;
    const int gid  = lane >> 2;
    const int tig  = lane & 3;

    const int r0  = w*16 + gid;
    const int qg0 = qt*128 + r0;
    const int qg1 = qg0 + 8;

    const int k_row  = (lane >> 4)*8 + (lane & 7);
    const int k_kofs = ((lane >> 3) & 1)*4;

    // Q fragments (pre-rounded; *0.125 is exponent-only, stays tf32-exact)
    const float* qb = g_q + (size_t)(bh*SEQ + qt*128)*DK;
    uint32_t qa[8][4];
#pragma unroll
    for (int ks = 0; ks < 8; ks++) {
        qa[ks][0] = __float_as_uint(qb[(size_t)r0*DK     + ks*8 + tig    ] * 0.125f);
        qa[ks][1] = __float_as_uint(qb[(size_t)(r0+8)*DK + ks*8 + tig    ] * 0.125f);
        qa[ks][2] = __float_as_uint(qb[(size_t)r0*DK     + ks*8 + tig + 4] * 0.125f);
        qa[ks][3] = __float_as_uint(qb[(size_t)(r0+8)*DK + ks*8 + tig + 4] * 0.125f);
    }

    float o[8][4];
#pragma unroll
    for (int dt = 0; dt < 8; dt++)
#pragma unroll
        for (int r = 0; r < 4; r++) o[dt][r] = 0.f;
    float m0 = -1e30f, m1 = -1e30f, l0 = 0.f, l1 = 0.f;

    const int nkt = 2*qt + 2;
    const float* kb0 = g_k + (size_t)bh*SEQ*DK;
    const float* vb0 = g_v + (size_t)bh*SEQ*DK;

    auto copy_kv = [&](int kt, int stage) {
        const uint32_t kbuf = sbase + (uint32_t)stage*AT_STAGE_FLOATS*4;
        const uint32_t vbuf = kbuf + 64*AT_KSTR*4;
        const float* kb = kb0 + (size_t)kt*64*DK;
        const float* vb = vb0 + (size_t)kt*64*DK;
#pragma unroll
        for (int i = 0; i < 4; i++) {
            const int f = tid + i*256;
            const int row = f >> 4;
            const int q4  = f & 15;
            cp_async16(kbuf + (uint32_t)(row*AT_KSTR + q4*4)*4, kb + row*DK + q4*4);
            cp_async16(vbuf + (uint32_t)(row*AT_VSTR + q4*4)*4, vb + row*DK + q4*4);
        }
        cp_commit();
    };

    copy_kv(0, 0);
    if (nkt > 1) copy_kv(1, 1);

    int cs = 0;
    for (int kt = 0; kt < nkt; kt++) {
        if (kt + 1 < nkt) {
            asm volatile("cp.async.wait_group 1;");
        } else {
            asm volatile("cp.async.wait_group 0;");
        }
        __syncthreads();        // stage cs ready; stage (cs+2)%3 free

        if (kt + 2 < nkt) {
            int ps = cs + 2; if (ps >= AT_NSTAGE) ps -= AT_NSTAGE;
            copy_kv(kt + 2, ps);
        }

        const uint32_t kbase = sbase + (uint32_t)cs*AT_STAGE_FLOATS*4;
        const float* Vs = atm + (size_t)cs*AT_STAGE_FLOATS + 64*AT_KSTR;

        // ---- S = Q K^T ----
        float s[8][4];
#pragma unroll
        for (int nt = 0; nt < 8; nt++)
#pragma unroll
            for (int r = 0; r < 4; r++) s[nt][r] = 0.f;

        const uint32_t kAddr = kbase + (uint32_t)(k_row*AT_KSTR + k_kofs)*4;
#pragma unroll
        for (int ks = 0; ks < 8; ks++) {
            const uint32_t ko = ks*32;
#pragma unroll
            for (int pair = 0; pair < 4; pair++) {
                uint32_t b00, b01, b10, b11;
                ldsm_x4(b00, b01, b10, b11,
                        kAddr + (uint32_t)pair*16*AT_KSTR*4 + ko);
                mma_tf32_16x8x8(s[2*pair][0], s[2*pair][1],
                                s[2*pair][2], s[2*pair][3],
                                qa[ks][0], qa[ks][1], qa[ks][2], qa[ks][3],
                                b00, b01);
                mma_tf32_16x8x8(s[2*pair+1][0], s[2*pair+1][1],
                                s[2*pair+1][2], s[2*pair+1][3],
                                qa[ks][0], qa[ks][1], qa[ks][2], qa[ks][3],
                                b10, b11);
            }
        }

        // ---- causal mask ----
        if (kt >= 2*qt) {
#pragma unroll
            for (int nt = 0; nt < 8; nt++) {
                const int kg = kt*64 + nt*8 + 2*tig;
                if (kg     > qg0) s[nt][0] = -1e30f;
                if (kg + 1 > qg0) s[nt][1] = -1e30f;
                if (kg     > qg1) s[nt][2] = -1e30f;
                if (kg + 1 > qg1) s[nt][3] = -1e30f;
            }
        }

        // ---- online softmax ----
        float t0 = -1e30f, t1 = -1e30f;
#pragma unroll
        for (int nt = 0; nt < 8; nt++) {
            t0 = fmaxf(t0, fmaxf(s[nt][0], s[nt][1]));
            t1 = fmaxf(t1, fmaxf(s[nt][2], s[nt][3]));
        }
        t0 = fmaxf(t0, SHFL_XOR(t0, 1)); t0 = fmaxf(t0, SHFL_XOR(t0, 2));
        t1 = fmaxf(t1, SHFL_XOR(t1, 1)); t1 = fmaxf(t1, SHFL_XOR(t1, 2));
        const float m0n = fmaxf(m0, t0), m1n = fmaxf(m1, t1);
        const float c0 = __expf(m0 - m0n), c1 = __expf(m1 - m1n);
        m0 = m0n; m1 = m1n;

        float sum0 = 0.f, sum1 = 0.f;
#pragma unroll
        for (int nt = 0; nt < 8; nt++) {
            float p0 = __expf(s[nt][0] - m0);
            float p1 = __expf(s[nt][1] - m0);
            float p2 = __expf(s[nt][2] - m1);
            float p3 = __expf(s[nt][3] - m1);
            sum0 += p0 + p1; sum1 += p2 + p3;
            s[nt][0] = __uint_as_float(to_tf32_u(p0));
            s[nt][1] = __uint_as_float(to_tf32_u(p1));
            s[nt][2] = __uint_as_float(to_tf32_u(p2));
            s[nt][3] = __uint_as_float(to_tf32_u(p3));
        }
        sum0 += SHFL_XOR(sum0, 1); sum0 += SHFL_XOR(sum0, 2);
        sum1 += SHFL_XOR(sum1, 1); sum1 += SHFL_XOR(sum1, 2);
        l0 = l0*c0 + sum0;
        l1 = l1*c1 + sum1;
#pragma unroll
        for (int dt = 0; dt < 8; dt++) {
            o[dt][0] *= c0; o[dt][1] *= c0;
            o[dt][2] *= c1; o[dt][3] *= c1;
        }

        // ---- O += P V (quad-shuffle P -> A-fragments) ----
        const int srcA = (lane & ~3) | (tig >> 1);
        const int srcB = srcA + 2;
        const bool odd = (tig & 1);
#pragma unroll
        for (int kp = 0; kp < 8; kp++) {
            const float x0 = SHFL(s[kp][0], srcA);
            const float x1 = SHFL(s[kp][1], srcA);
            const float x2 = SHFL(s[kp][2], srcA);
            const float x3 = SHFL(s[kp][3], srcA);
            const float y0 = SHFL(s[kp][0], srcB);
            const float y1 = SHFL(s[kp][1], srcB);
            const float y2 = SHFL(s[kp][2], srcB);
            const float y3 = SHFL(s[kp][3], srcB);
            const uint32_t a0 = __float_as_uint(odd ? x1 : x0);
            const uint32_t a1 = __float_as_uint(odd ? x3 : x2);
            const uint32_t a2 = __float_as_uint(odd ? y1 : y0);
            const uint32_t a3 = __float_as_uint(odd ? y3 : y2);
#pragma unroll
            for (int dt = 0; dt < 8; dt++) {
                const uint32_t b0 =
                    __float_as_uint(Vs[(kp*8 + tig    )*AT_VSTR + dt*8 + gid]);
                const uint32_t b1 =
                    __float_as_uint(Vs[(kp*8 + tig + 4)*AT_VSTR + dt*8 + gid]);
                mma_tf32_16x8x8(o[dt][0], o[dt][1], o[dt][2], o[dt][3],
                                a0, a1, a2, a3, b0, b1);
            }
        }

        cs = cs + 1; if (cs >= AT_NSTAGE) cs -= AT_NSTAGE;
    }

    // ---- finalize: O /= l, tf32-round (O-proj input), write [B,S,D] ----
    const float inv0 = 1.f / l0, inv1 = 1.f / l1;
    const int b = bh >> 4, h = bh & 15;
    float* ob0 = g_attn + (size_t)(b*SEQ + qg0)*DMODEL + h*DK;
    float* ob1 = g_attn + (size_t)(b*SEQ + qg1)*DMODEL + h*DK;
#pragma unroll
    for (int dt = 0; dt < 8; dt++) {
        const int d = dt*8 + 2*tig;
        *(float2*)(ob0 + d) = make_float2(to_tf32(o[dt][0]*inv0),
                                          to_tf32(o[dt][1]*inv0));
        *(float2*)(ob1 + d) = make_float2(to_tf32(o[dt][2]*inv1),
                                          to_tf32(o[dt][3]*inv1));
    }
}

// ---------------------------------------------------------------------------
// Launch.  Inputs: x, mask, w_qkv_w, w_qkv_b, w_o_w, w_o_b
// ---------------------------------------------------------------------------
extern "C" void kernel_launch(void* const* d_in, const int* in_sizes, int n_in,
                              void* d_out, int out_size)
{
    const float* x      = (const float*)d_in[0];
    const float* wqkv   = (const float*)d_in[2];
    const float* bqkv   = (const float*)d_in[3];
    const float* wo     = (const float*)d_in[4];
    const float* bo     = (const float*)d_in[5];
    float* out = (float*)d_out;

    float *p_attn, *p_x, *p_wqkv, *p_wo;
    cudaGetSymbolAddress((void**)&p_attn, g_attn);
    cudaGetSymbolAddress((void**)&p_x,    g_x);
    cudaGetSymbolAddress((void**)&p_wqkv, g_wqkv);
    cudaGetSymbolAddress((void**)&p_wo,   g_wo);

    cudaFuncSetAttribute(mma_gemm, cudaFuncAttributeMaxDynamicSharedMemorySize,
                         GEMM_SMEM_BYTES);
    cudaFuncSetAttribute(flash_attn_mma,
                         cudaFuncAttributeMaxDynamicSharedMemorySize,
                         AT_SMEM_BYTES);

    // 0) pre-round inputs/weights to tf32
    roundcopy<<<2048, 256>>>((const float4*)x,    (float4*)p_x,    M_TOK*DMODEL/4);
    roundcopy<<<2048, 256>>>((const float4*)wqkv, (float4*)p_wqkv, 3*DMODEL*DMODEL/4);
    roundcopy<<<1024, 256>>>((const float4*)wo,   (float4*)p_wo,   DMODEL*DMODEL/4);

    // 1) QKV projection -> g_q/g_k/g_v (tf32-rounded at write)
    {
        dim3 grid(3*DMODEL/BN, M_TOK/BM);   // (24, 32)
        mma_gemm<<<grid, 256, GEMM_SMEM_BYTES>>>(p_x, p_wqkv, bqkv, nullptr,
                                                 M_TOK, 3*DMODEL, DMODEL, 0);
    }
    // 2) Causal flash attention -> g_attn (tf32-rounded at write)
    {
        dim3 grid(SEQ/128, BATCH*NHEADS);   // (16, 32)
        flash_attn_mma<<<grid, 256, AT_SMEM_BYTES>>>();
    }
    // 3) Output projection -> d_out (full fp32 epilogue)
    {
        dim3 grid(DMODEL/BN, M_TOK/BM);     // (8, 32)
        mma_gemm<<<grid, 256, GEMM_SMEM_BYTES>>>(p_attn, p_wo, bo, out,
                                                 M_TOK, DMODEL, DMODEL, 1);
    }
}

// round 11
// speedup vs baseline: 9.3563x; 1.7468x over previous
#include <cuda_runtime.h>
#include <cuda_fp16.h>
#include <cstdint>

// Problem constants
#define BATCH 2
#define SEQ   2048
#define DMODEL 1024
#define NHEADS 16
#define DK 64
#define M_TOK (BATCH*SEQ)          // 4096

// Scratch (no allocations allowed -> __device__ globals).  All fp16.
__device__ __half g_q[BATCH*NHEADS*SEQ*DK];     // pre-scaled by 0.125
__device__ __half g_k[BATCH*NHEADS*SEQ*DK];
__device__ __half g_v[BATCH*NHEADS*SEQ*DK];
__device__ __half g_attn[M_TOK*DMODEL];
__device__ __half g_x[M_TOK*DMODEL];
__device__ __half g_wqkv[3*DMODEL*DMODEL];
__device__ __half g_wo[DMODEL*DMODEL];

// ---------------------------------------------------------------------------
// helpers
// ---------------------------------------------------------------------------
__device__ __forceinline__ uint32_t smem_u32(const void* p) {
    uint32_t a;
    asm("{ .reg .u64 t; cvta.to.shared.u64 t, %1; cvt.u32.u64 %0, t; }"
        : "=r"(a) : "l"(p));
    return a;
}
__device__ __forceinline__ void cp_async16(uint32_t saddr, const void* gaddr) {
    asm volatile("cp.async.cg.shared.global [%0], [%1], 16;"
                 :: "r"(saddr), "l"(gaddr));
}
__device__ __forceinline__ void cp_commit() {
    asm volatile("cp.async.commit_group;");
}
__device__ __forceinline__ void ldsm_x4(uint32_t& r0, uint32_t& r1,
                                        uint32_t& r2, uint32_t& r3, uint32_t addr) {
    asm volatile("ldmatrix.sync.aligned.m8n8.x4.shared.b16 {%0,%1,%2,%3}, [%4];"
                 : "=r"(r0), "=r"(r1), "=r"(r2), "=r"(r3) : "r"(addr));
}
__device__ __forceinline__ void ldsm_x4_t(uint32_t& r0, uint32_t& r1,
                                          uint32_t& r2, uint32_t& r3, uint32_t addr) {
    asm volatile("ldmatrix.sync.aligned.m8n8.x4.trans.shared.b16 {%0,%1,%2,%3}, [%4];"
                 : "=r"(r0), "=r"(r1), "=r"(r2), "=r"(r3) : "r"(addr));
}
__device__ __forceinline__ uint32_t h2pack(float lo, float hi) {
    __half2 h = __floats2half2_rn(lo, hi);   // .x = lo (bits 0-15)
    return *(uint32_t*)&h;
}
__device__ __forceinline__ void mma_f16_16x8x16(
    float& d0, float& d1, float& d2, float& d3,
    uint32_t a0, uint32_t a1, uint32_t a2, uint32_t a3,
    uint32_t b0, uint32_t b1)
{
    asm volatile(
        "mma.sync.aligned.m16n8k16.row.col.f32.f16.f16.f32 "
        "{%0,%1,%2,%3}, {%4,%5,%6,%7}, {%8,%9}, {%0,%1,%2,%3};"
        : "+f"(d0), "+f"(d1), "+f"(d2), "+f"(d3)
        : "r"(a0), "r"(a1), "r"(a2), "r"(a3), "r"(b0), "r"(b1));
}

#define SHFL_XOR(v, m) __shfl_xor_sync(0xffffffffu, v, m)

// ---------------------------------------------------------------------------
// Pre-pass: fp32 -> fp16 round (float4 -> 2x half2, grid-stride).
// ---------------------------------------------------------------------------
__global__ __launch_bounds__(256)
void roundcopy_h(const float4* __restrict__ src, __half2* __restrict__ dst, int n4)
{
    for (int i = blockIdx.x*blockDim.x + threadIdx.x; i < n4;
         i += gridDim.x*blockDim.x) {
        float4 v = src[i];
        dst[2*i]   = __floats2half2_rn(v.x, v.y);
        dst[2*i+1] = __floats2half2_rn(v.z, v.w);
    }
}

// ===========================================================================
// fp16 tensor-core GEMM: C = A @ B^T + bias (fp32 accum).
// A: [M,K] fp16 row-major, B: [N,K] fp16 row-major. M,N %128==0, K %32==0 (>=64).
// 128x128 tile, BK=32 (2 k-steps of 16), 3-stage cp.async pipeline,
// ldmatrix fragments, 256 threads (8 warps 2x4, 64x32 per warp).
// smem row stride 40 halves (80 B) -> ldmatrix conflict-free (banks 20r%32).
// mode 0: scatter fp16 into g_q (x0.125) / g_k / g_v; mode 1: fp32 C write.
// ===========================================================================
#define BM 128
#define BN 128
#define OPB  (128*40*2)                  // 10240 B per operand per stage
#define STAGEB (2*OPB)                   // 20480 B
#define NSTAGE 3
#define GEMM_SMEM_BYTES (NSTAGE*STAGEB)  // 61440 B

__global__ __launch_bounds__(256)
void mma_gemm(const __half* __restrict__ A, const __half* __restrict__ B,
              const float* __restrict__ bias, float* __restrict__ C,
              int M, int N, int K, int mode)
{
    extern __shared__ char smx[];
    const uint32_t sbase = smem_u32(smx);

    const int tid = threadIdx.x;
    const int wid = tid >> 5;
    const int lane = tid & 31;
    const int gid = lane >> 2;
    const int tig = lane & 3;
    const int warpM = wid >> 2;
    const int warpN = wid & 3;
    const int bm = blockIdx.y, bn = blockIdx.x;

    const __half* Abase = A + (size_t)(bm*BM)*K;
    const __half* Bbase = B + (size_t)(bn*BN)*K;

    // copy: 512 16B-chunks per operand (128 rows x 4), 2 per thread
    const int crow = tid >> 2;           // 0..63 (+64 on second iter? no: idx)
    const int cc4  = tid & 3;

    // ldmatrix lane address components
    const int a_row  = lane & 15;
    const int a_colB = (lane >> 4)*16;
    const int b_row  = (lane & 7) + ((lane >> 4) & 1)*8;
    const int b_colB = ((lane >> 3) & 1)*16;

    float acc[4][4][4];
#pragma unroll
    for (int i = 0; i < 4; i++)
#pragma unroll
        for (int j = 0; j < 4; j++)
#pragma unroll
            for (int r = 0; r < 4; r++) acc[i][j][r] = 0.f;

    const int NC = K / 32;

    auto copy_stage = [&](int c, int st) {
        const uint32_t abuf = sbase + (uint32_t)st*STAGEB;
        const uint32_t bbuf = abuf + OPB;
        const int k0 = c * 32;
#pragma unroll
        for (int i = 0; i < 2; i++) {
            const int idx = tid + i*256;
            const int row = idx >> 2;            // 0..127
            const int c4  = idx & 3;
            const uint32_t soff = (uint32_t)(row*80 + c4*16);
            cp_async16(abuf + soff, Abase + (size_t)row*K + k0 + c4*8);
            cp_async16(bbuf + soff, Bbase + (size_t)row*K + k0 + c4*8);
        }
        cp_commit();
    };

    copy_stage(0, 0);
    copy_stage(1, 1);

    int cs = 0;
    for (int c = 0; c < NC; c++) {
        if (c + 1 < NC) {
            asm volatile("cp.async.wait_group 1;");
        } else {
            asm volatile("cp.async.wait_group 0;");
        }
        __syncthreads();

        if (c + 2 < NC) {
            int ps = cs + 2; if (ps >= NSTAGE) ps -= NSTAGE;
            copy_stage(c + 2, ps);
        }

        const uint32_t stage_base = sbase + (uint32_t)cs*STAGEB;
        const uint32_t aAddr = stage_base
            + (uint32_t)((warpM*64 + a_row)*80 + a_colB);
        const uint32_t bAddr = stage_base + OPB
            + (uint32_t)((warpN*32 + b_row)*80 + b_colB);

#pragma unroll
        for (int ks = 0; ks < 2; ks++) {
            const uint32_t ko = ks*32;           // 16 halves
            uint32_t bf[2][4];
            ldsm_x4(bf[0][0], bf[0][1], bf[0][2], bf[0][3], bAddr + ko);
            ldsm_x4(bf[1][0], bf[1][1], bf[1][2], bf[1][3],
                    bAddr + 16*80 + ko);
#pragma unroll
            for (int mt = 0; mt < 4; mt++) {
                uint32_t a0, a1, a2, a3;
                ldsm_x4(a0, a1, a2, a3, aAddr + (uint32_t)mt*16*80 + ko);
#pragma unroll
                for (int ntp = 0; ntp < 2; ntp++) {
#pragma unroll
                    for (int sub = 0; sub < 2; sub++) {
                        const int nt = ntp*2 + sub;
                        mma_f16_16x8x16(acc[mt][nt][0], acc[mt][nt][1],
                                        acc[mt][nt][2], acc[mt][nt][3],
                                        a0, a1, a2, a3,
                                        bf[ntp][sub*2], bf[ntp][sub*2+1]);
                    }
                }
            }
        }
        cs = cs + 1; if (cs >= NSTAGE) cs -= NSTAGE;
    }

    // ---- epilogue ----
#pragma unroll
    for (int mt = 0; mt < 4; mt++) {
        const int row0 = bm*BM + warpM*64 + mt*16 + gid;
#pragma unroll
        for (int nt = 0; nt < 4; nt++) {
            const int col = bn*BN + warpN*32 + nt*8 + tig*2;
            const float bz0 = bias[col], bz1 = bias[col+1];
#pragma unroll
            for (int half = 0; half < 2; half++) {
                const int row = row0 + half*8;
                float v0 = acc[mt][nt][half*2+0] + bz0;
                float v1 = acc[mt][nt][half*2+1] + bz1;
                if (mode == 1) {
                    *(float2*)(C + (size_t)row*N + col) = make_float2(v0, v1);
                } else {
                    const int sel = col >> 10;
                    if (sel == 0) { v0 *= 0.125f; v1 *= 0.125f; }  // pre-scale Q
                    const int d2  = col & 1023;
                    const int h   = d2 >> 6;
                    const int dk  = d2 & 63;
                    const int b   = row >> 11;
                    const int s   = row & 2047;
                    __half* dst = (sel == 0) ? g_q : (sel == 1) ? g_k : g_v;
                    *(__half2*)(dst + ((size_t)(((b<<4)+h)*SEQ + s))*DK + dk)
                        = __floats2half2_rn(v0, v1);
                }
            }
        }
    }
}

// ===========================================================================
// fp16 tensor-core causal flash attention (mma.m16n8k16, fp32 softmax/accum).
// 3-stage cp.async K/V pipeline, ldmatrix K frags, ldmatrix.trans V frags.
// P A-fragments come directly from score C-fragments (FA2 identity) — no
// shuffles, no smem round-trip. Q pre-scaled by 0.125 in the QKV epilogue.
// K/V tiles 64x64 fp16, smem row stride 72 halves (144 B, banks 4r%32).
// ===========================================================================
#define AT_OPB (64*72*2)                       // 9216 B per operand per stage
#define AT_STAGEB (2*AT_OPB)                   // 18432 B
#define AT_NSTAGE 3
#define AT_SMEM_BYTES (AT_NSTAGE*AT_STAGEB)    // 55296 B

__global__ __launch_bounds__(256, 2)
void flash_attn_mma()
{
    extern __shared__ char atm[];
    const uint32_t sbase = smem_u32(atm);

    const int qt  = (int)gridDim.x - 1 - (int)blockIdx.x;   // heavy tiles first
    const int bh  = blockIdx.y;
    const int tid = threadIdx.x;
    const int w    = tid >> 5;
    const int lane = tid & 31;
    const int gid  = lane >> 2;
    const int tig  = lane & 3;

    const int r0  = w*16 + gid;
    const int qg0 = qt*128 + r0;
    const int qg1 = qg0 + 8;

    // ldmatrix lane address components
    const int k_row  = (lane & 7) + ((lane >> 4) & 1)*8;   // QK (non-trans)
    const int k_colB = ((lane >> 3) & 1)*16;
    const int v_row  = (lane & 7) + ((lane >> 3) & 1)*8;   // PV (trans)
    const int v_colB = (lane >> 4)*16;

    // Q fragments (fp16, pre-scaled): 4 k-steps x 4 half2 regs
    const __half* qb = g_q + (size_t)(bh*SEQ + qt*128)*DK;
    uint32_t qa[4][4];
#pragma unroll
    for (int ks = 0; ks < 4; ks++) {
        qa[ks][0] = *(const uint32_t*)(qb + (size_t)r0*DK     + ks*16 + 2*tig);
        qa[ks][1] = *(const uint32_t*)(qb + (size_t)(r0+8)*DK + ks*16 + 2*tig);
        qa[ks][2] = *(const uint32_t*)(qb + (size_t)r0*DK     + ks*16 + 2*tig + 8);
        qa[ks][3] = *(const uint32_t*)(qb + (size_t)(r0+8)*DK + ks*16 + 2*tig + 8);
    }

    float o[8][4];
#pragma unroll
    for (int dt = 0; dt < 8; dt++)
#pragma unroll
        for (int r = 0; r < 4; r++) o[dt][r] = 0.f;
    float m0 = -1e30f, m1 = -1e30f, l0 = 0.f, l1 = 0.f;

    const int nkt = 2*qt + 2;
    const __half* kb0 = g_k + (size_t)bh*SEQ*DK;
    const __half* vb0 = g_v + (size_t)bh*SEQ*DK;

    auto copy_kv = [&](int kt, int stage) {
        const uint32_t kbuf = sbase + (uint32_t)stage*AT_STAGEB;
        const uint32_t vbuf = kbuf + AT_OPB;
        const __half* kb = kb0 + (size_t)kt*64*DK;
        const __half* vb = vb0 + (size_t)kt*64*DK;
#pragma unroll
        for (int i = 0; i < 2; i++) {
            const int idx = tid + i*256;
            const int row = idx >> 3;            // 0..63
            const int c8  = idx & 7;
            const uint32_t soff = (uint32_t)(row*144 + c8*16);
            cp_async16(kbuf + soff, kb + row*DK + c8*8);
            cp_async16(vbuf + soff, vb + row*DK + c8*8);
        }
        cp_commit();
    };

    copy_kv(0, 0);
    if (nkt > 1) copy_kv(1, 1);

    int cs = 0;
    for (int kt = 0; kt < nkt; kt++) {
        if (kt + 1 < nkt) {
            asm volatile("cp.async.wait_group 1;");
        } else {
            asm volatile("cp.async.wait_group 0;");
        }
        __syncthreads();

        if (kt + 2 < nkt) {
            int ps = cs + 2; if (ps >= AT_NSTAGE) ps -= AT_NSTAGE;
            copy_kv(kt + 2, ps);
        }

        const uint32_t kstage = sbase + (uint32_t)cs*AT_STAGEB;
        const uint32_t vstage = kstage + AT_OPB;

        // ---- S = Q K^T (scale folded into Q) ----
        float s[8][4];
#pragma unroll
        for (int nt = 0; nt < 8; nt++)
#pragma unroll
            for (int r = 0; r < 4; r++) s[nt][r] = 0.f;

        const uint32_t kAddr = kstage + (uint32_t)(k_row*144 + k_colB);
#pragma unroll
        for (int ks = 0; ks < 4; ks++) {
            const uint32_t ko = ks*32;
#pragma unroll
            for (int p = 0; p < 4; p++) {
                uint32_t b00, b01, b10, b11;
                ldsm_x4(b00, b01, b10, b11,
                        kAddr + (uint32_t)p*16*144 + ko);
                mma_f16_16x8x16(s[2*p][0], s[2*p][1], s[2*p][2], s[2*p][3],
                                qa[ks][0], qa[ks][1], qa[ks][2], qa[ks][3],
                                b00, b01);
                mma_f16_16x8x16(s[2*p+1][0], s[2*p+1][1],
                                s[2*p+1][2], s[2*p+1][3],
                                qa[ks][0], qa[ks][1], qa[ks][2], qa[ks][3],
                                b10, b11);
            }
        }

        // ---- causal mask ----
        if (kt >= 2*qt) {
#pragma unroll
            for (int nt = 0; nt < 8; nt++) {
                const int kg = kt*64 + nt*8 + 2*tig;
                if (kg     > qg0) s[nt][0] = -1e30f;
                if (kg + 1 > qg0) s[nt][1] = -1e30f;
                if (kg     > qg1) s[nt][2] = -1e30f;
                if (kg + 1 > qg1) s[nt][3] = -1e30f;
            }
        }

        // ---- online softmax (fp32) ----
        float t0 = -1e30f, t1 = -1e30f;
#pragma unroll
        for (int nt = 0; nt < 8; nt++) {
            t0 = fmaxf(t0, fmaxf(s[nt][0], s[nt][1]));
            t1 = fmaxf(t1, fmaxf(s[nt][2], s[nt][3]));
        }
        t0 = fmaxf(t0, SHFL_XOR(t0, 1)); t0 = fmaxf(t0, SHFL_XOR(t0, 2));
        t1 = fmaxf(t1, SHFL_XOR(t1, 1)); t1 = fmaxf(t1, SHFL_XOR(t1, 2));
        const float m0n = fmaxf(m0, t0), m1n = fmaxf(m1, t1);
        const float c0 = __expf(m0 - m0n), c1 = __expf(m1 - m1n);
        m0 = m0n; m1 = m1n;

        float sum0 = 0.f, sum1 = 0.f;
#pragma unroll
        for (int nt = 0; nt < 8; nt++) {
            s[nt][0] = __expf(s[nt][0] - m0);
            s[nt][1] = __expf(s[nt][1] - m0);
            s[nt][2] = __expf(s[nt][2] - m1);
            s[nt][3] = __expf(s[nt][3] - m1);
            sum0 += s[nt][0] + s[nt][1];
            sum1 += s[nt][2] + s[nt][3];
        }
        sum0 += SHFL_XOR(sum0, 1); sum0 += SHFL_XOR(sum0, 2);
        sum1 += SHFL_XOR(sum1, 1); sum1 += SHFL_XOR(sum1, 2);
        l0 = l0*c0 + sum0;
        l1 = l1*c1 + sum1;
#pragma unroll
        for (int dt = 0; dt < 8; dt++) {
            o[dt][0] *= c0; o[dt][1] *= c0;
            o[dt][2] *= c1; o[dt][3] *= c1;
        }

        // ---- O += P V (P A-frags = score C-frags, converted; V via trans) --
        const uint32_t vAddr = vstage + (uint32_t)(v_row*144 + v_colB);
#pragma unroll
        for (int kp = 0; kp < 4; kp++) {
            const uint32_t pa0 = h2pack(s[2*kp  ][0], s[2*kp  ][1]);
            const uint32_t pa1 = h2pack(s[2*kp  ][2], s[2*kp  ][3]);
            const uint32_t pa2 = h2pack(s[2*kp+1][0], s[2*kp+1][1]);
            const uint32_t pa3 = h2pack(s[2*kp+1][2], s[2*kp+1][3]);
#pragma unroll
            for (int g = 0; g < 4; g++) {
                uint32_t v00, v01, v10, v11;
                ldsm_x4_t(v00, v01, v10, v11,
                          vAddr + (uint32_t)kp*16*144 + g*32);
                mma_f16_16x8x16(o[2*g][0], o[2*g][1], o[2*g][2], o[2*g][3],
                                pa0, pa1, pa2, pa3, v00, v01);
                mma_f16_16x8x16(o[2*g+1][0], o[2*g+1][1],
                                o[2*g+1][2], o[2*g+1][3],
                                pa0, pa1, pa2, pa3, v10, v11);
            }
        }

        cs = cs + 1; if (cs >= AT_NSTAGE) cs -= AT_NSTAGE;
    }

    // ---- finalize: O /= l, fp16-round (O-proj input), write [B,S,D] ----
    const float inv0 = 1.f / l0, inv1 = 1.f / l1;
    const int b = bh >> 4, h = bh & 15;
    __half* ob0 = g_attn + (size_t)(b*SEQ + qg0)*DMODEL + h*DK;
    __half* ob1 = g_attn + (size_t)(b*SEQ + qg1)*DMODEL + h*DK;
#pragma unroll
    for (int dt = 0; dt < 8; dt++) {
        const int d = dt*8 + 2*tig;
        *(__half2*)(ob0 + d) = __floats2half2_rn(o[dt][0]*inv0, o[dt][1]*inv0);
        *(__half2*)(ob1 + d) = __floats2half2_rn(o[dt][2]*inv1, o[dt][3]*inv1);
    }
}

// ---------------------------------------------------------------------------
// Launch.  Inputs: x, mask, w_qkv_w, w_qkv_b, w_o_w, w_o_b
// ---------------------------------------------------------------------------
extern "C" void kernel_launch(void* const* d_in, const int* in_sizes, int n_in,
                              void* d_out, int out_size)
{
    const float* x      = (const float*)d_in[0];
    const float* wqkv   = (const float*)d_in[2];
    const float* bqkv   = (const float*)d_in[3];
    const float* wo     = (const float*)d_in[4];
    const float* bo     = (const float*)d_in[5];
    float* out = (float*)d_out;

    __half *p_attn, *p_x, *p_wqkv, *p_wo;
    cudaGetSymbolAddress((void**)&p_attn, g_attn);
    cudaGetSymbolAddress((void**)&p_x,    g_x);
    cudaGetSymbolAddress((void**)&p_wqkv, g_wqkv);
    cudaGetSymbolAddress((void**)&p_wo,   g_wo);

    cudaFuncSetAttribute(mma_gemm, cudaFuncAttributeMaxDynamicSharedMemorySize,
                         GEMM_SMEM_BYTES);
    cudaFuncSetAttribute(flash_attn_mma,
                         cudaFuncAttributeMaxDynamicSharedMemorySize,
                         AT_SMEM_BYTES);

    // 0) pre-round inputs/weights to fp16
    roundcopy_h<<<2048, 256>>>((const float4*)x,    (__half2*)p_x,
                               M_TOK*DMODEL/4);
    roundcopy_h<<<2048, 256>>>((const float4*)wqkv, (__half2*)p_wqkv,
                               3*DMODEL*DMODEL/4);
    roundcopy_h<<<1024, 256>>>((const float4*)wo,   (__half2*)p_wo,
                               DMODEL*DMODEL/4);

    // 1) QKV projection -> g_q (x0.125) / g_k / g_v (fp16)
    {
        dim3 grid(3*DMODEL/BN, M_TOK/BM);   // (24, 32)
        mma_gemm<<<grid, 256, GEMM_SMEM_BYTES>>>(p_x, p_wqkv, bqkv, nullptr,
                                                 M_TOK, 3*DMODEL, DMODEL, 0);
    }
    // 2) Causal flash attention -> g_attn (fp16)
    {
        dim3 grid(SEQ/128, BATCH*NHEADS);   // (16, 32)
        flash_attn_mma<<<grid, 256, AT_SMEM_BYTES>>>();
    }
    // 3) Output projection -> d_out (fp32)
    {
        dim3 grid(DMODEL/BN, M_TOK/BM);     // (8, 32)
        mma_gemm<<<grid, 256, GEMM_SMEM_BYTES>>>(p_attn, p_wo, bo, out,
                                                 M_TOK, DMODEL, DMODEL, 1);
    }
}

// round 13
// speedup vs baseline: 10.6681x; 1.1402x over previous
#include <cuda_runtime.h>
#include <cuda_fp16.h>
#include <cstdint>

// Problem constants
#define BATCH 2
#define SEQ   2048
#define DMODEL 1024
#define NHEADS 16
#define DK 64
#define M_TOK (BATCH*SEQ)          // 4096

// Scratch (no allocations allowed -> __device__ globals).  All fp16.
__device__ __half g_q[BATCH*NHEADS*SEQ*DK];     // pre-scaled by 0.125
__device__ __half g_k[BATCH*NHEADS*SEQ*DK];
__device__ __half g_v[BATCH*NHEADS*SEQ*DK];
__device__ __half g_attn[M_TOK*DMODEL];
__device__ __half g_x[M_TOK*DMODEL];
__device__ __half g_wqkv[3*DMODEL*DMODEL];
__device__ __half g_wo[DMODEL*DMODEL];

// ---------------------------------------------------------------------------
// helpers
// ---------------------------------------------------------------------------
__device__ __forceinline__ uint32_t smem_u32(const void* p) {
    uint32_t a;
    asm("{ .reg .u64 t; cvta.to.shared.u64 t, %1; cvt.u32.u64 %0, t; }"
        : "=r"(a) : "l"(p));
    return a;
}
__device__ __forceinline__ void cp_async16(uint32_t saddr, const void* gaddr) {
    asm volatile("cp.async.cg.shared.global [%0], [%1], 16;"
                 :: "r"(saddr), "l"(gaddr));
}
__device__ __forceinline__ void cp_commit() {
    asm volatile("cp.async.commit_group;");
}
__device__ __forceinline__ void ldsm_x4(uint32_t& r0, uint32_t& r1,
                                        uint32_t& r2, uint32_t& r3, uint32_t addr) {
    asm volatile("ldmatrix.sync.aligned.m8n8.x4.shared.b16 {%0,%1,%2,%3}, [%4];"
                 : "=r"(r0), "=r"(r1), "=r"(r2), "=r"(r3) : "r"(addr));
}
__device__ __forceinline__ void ldsm_x4_t(uint32_t& r0, uint32_t& r1,
                                          uint32_t& r2, uint32_t& r3, uint32_t addr) {
    asm volatile("ldmatrix.sync.aligned.m8n8.x4.trans.shared.b16 {%0,%1,%2,%3}, [%4];"
                 : "=r"(r0), "=r"(r1), "=r"(r2), "=r"(r3) : "r"(addr));
}
__device__ __forceinline__ uint32_t h2pack(float lo, float hi) {
    __half2 h = __floats2half2_rn(lo, hi);   // .x = lo (bits 0-15)
    return *(uint32_t*)&h;
}
__device__ __forceinline__ void mma_f16_16x8x16(
    float& d0, float& d1, float& d2, float& d3,
    uint32_t a0, uint32_t a1, uint32_t a2, uint32_t a3,
    uint32_t b0, uint32_t b1)
{
    asm volatile(
        "mma.sync.aligned.m16n8k16.row.col.f32.f16.f16.f32 "
        "{%0,%1,%2,%3}, {%4,%5,%6,%7}, {%8,%9}, {%0,%1,%2,%3};"
        : "+f"(d0), "+f"(d1), "+f"(d2), "+f"(d3)
        : "r"(a0), "r"(a1), "r"(a2), "r"(a3), "r"(b0), "r"(b1));
}

#define SHFL_XOR(v, m) __shfl_xor_sync(0xffffffffu, v, m)

// ---------------------------------------------------------------------------
// Pre-pass (single launch): fp32 -> fp16 round for x, w_qkv, w_o.
// ---------------------------------------------------------------------------
#define N4_X    (M_TOK*DMODEL/4)            // 1048576
#define N4_WQKV (3*DMODEL*DMODEL/4)         // 786432
#define N4_WO   (DMODEL*DMODEL/4)           // 262144
#define N4_TOT  (N4_X + N4_WQKV + N4_WO)    // 2097152

__global__ __launch_bounds__(256)
void roundcopy_all(const float4* __restrict__ sx, const float4* __restrict__ swq,
                   const float4* __restrict__ swo)
{
    __half2 *dx, *dwq, *dwo;
    dx  = (__half2*)g_x;
    dwq = (__half2*)g_wqkv;
    dwo = (__half2*)g_wo;
    for (int i = blockIdx.x*blockDim.x + threadIdx.x; i < N4_TOT;
         i += gridDim.x*blockDim.x) {
        const float4* s; __half2* d; int j;
        if (i < N4_X)                { s = sx;  d = dx;  j = i; }
        else if (i < N4_X + N4_WQKV) { s = swq; d = dwq; j = i - N4_X; }
        else                         { s = swo; d = dwo; j = i - N4_X - N4_WQKV; }
        float4 v = s[j];
        d[2*j]   = __floats2half2_rn(v.x, v.y);
        d[2*j+1] = __floats2half2_rn(v.z, v.w);
    }
}

// ===========================================================================
// fp16 tensor-core GEMM: C = A @ B^T + bias (fp32 accum).
// A: [M,K] fp16 row-major, B: [N,K] fp16 row-major. M,N %128==0, K %64==0.
// 128x128 tile, BK=64 (4 k-steps of 16), 3-stage cp.async pipeline,
// ldmatrix fragments, 256 threads (8 warps 2x4, 64x32 per warp).
// smem row stride 72 halves (144 B) -> ldmatrix bank pattern 4r, conflict-free.
// mode 0: scatter fp16 into g_q (x0.125) / g_k / g_v; mode 1: fp32 C write.
// ===========================================================================
#define BM 128
#define BN 128
#define ROWB 144                         // bytes per smem row (72 halves)
#define OPB  (128*ROWB)                  // 18432 B per operand per stage
#define STAGEB (2*OPB)                   // 36864 B
#define NSTAGE 3
#define GEMM_SMEM_BYTES (NSTAGE*STAGEB)  // 110592 B

__global__ __launch_bounds__(256)
void mma_gemm(const __half* __restrict__ A, const __half* __restrict__ B,
              const float* __restrict__ bias, float* __restrict__ C,
              int M, int N, int K, int mode)
{
    extern __shared__ char smx[];
    const uint32_t sbase = smem_u32(smx);

    const int tid = threadIdx.x;
    const int wid = tid >> 5;
    const int lane = tid & 31;
    const int gid = lane >> 2;
    const int tig = lane & 3;
    const int warpM = wid >> 2;
    const int warpN = wid & 3;
    const int bm = blockIdx.y, bn = blockIdx.x;

    const __half* Abase = A + (size_t)(bm*BM)*K;
    const __half* Bbase = B + (size_t)(bn*BN)*K;

    // ldmatrix lane address components
    const int a_row  = lane & 15;
    const int a_colB = (lane >> 4)*16;
    const int b_row  = (lane & 7) + ((lane >> 4) & 1)*8;
    const int b_colB = ((lane >> 3) & 1)*16;

    float acc[4][4][4];
#pragma unroll
    for (int i = 0; i < 4; i++)
#pragma unroll
        for (int j = 0; j < 4; j++)
#pragma unroll
            for (int r = 0; r < 4; r++) acc[i][j][r] = 0.f;

    const int NC = K / 64;

    // copy: 1024 16B-chunks per operand (128 rows x 8), 4 per thread per op
    auto copy_stage = [&](int c, int st) {
        const uint32_t abuf = sbase + (uint32_t)st*STAGEB;
        const uint32_t bbuf = abuf + OPB;
        const int k0 = c * 64;
#pragma unroll
        for (int i = 0; i < 4; i++) {
            const int idx = tid + i*256;
            const int row = idx >> 3;            // 0..127
            const int c8  = idx & 7;
            const uint32_t soff = (uint32_t)(row*ROWB + c8*16);
            cp_async16(abuf + soff, Abase + (size_t)row*K + k0 + c8*8);
            cp_async16(bbuf + soff, Bbase + (size_t)row*K + k0 + c8*8);
        }
        cp_commit();
    };

    copy_stage(0, 0);
    copy_stage(1, 1);

    int cs = 0;
    for (int c = 0; c < NC; c++) {
        if (c + 1 < NC) {
            asm volatile("cp.async.wait_group 1;");
        } else {
            asm volatile("cp.async.wait_group 0;");
        }
        __syncthreads();        // stage cs ready; stage (cs+2)%3 free

        if (c + 2 < NC) {
            int ps = cs + 2; if (ps >= NSTAGE) ps -= NSTAGE;
            copy_stage(c + 2, ps);
        }

        const uint32_t stage_base = sbase + (uint32_t)cs*STAGEB;
        const uint32_t aAddr = stage_base
            + (uint32_t)((warpM*64 + a_row)*ROWB + a_colB);
        const uint32_t bAddr = stage_base + OPB
            + (uint32_t)((warpN*32 + b_row)*ROWB + b_colB);

#pragma unroll
        for (int ks = 0; ks < 4; ks++) {
            const uint32_t ko = ks*32;           // 16 halves
            uint32_t bf[2][4];
            ldsm_x4(bf[0][0], bf[0][1], bf[0][2], bf[0][3], bAddr + ko);
            ldsm_x4(bf[1][0], bf[1][1], bf[1][2], bf[1][3],
                    bAddr + 16*ROWB + ko);
#pragma unroll
            for (int mt = 0; mt < 4; mt++) {
                uint32_t a0, a1, a2, a3;
                ldsm_x4(a0, a1, a2, a3, aAddr + (uint32_t)mt*16*ROWB + ko);
#pragma unroll
                for (int ntp = 0; ntp < 2; ntp++) {
#pragma unroll
                    for (int sub = 0; sub < 2; sub++) {
                        const int nt = ntp*2 + sub;
                        mma_f16_16x8x16(acc[mt][nt][0], acc[mt][nt][1],
                                        acc[mt][nt][2], acc[mt][nt][3],
                                        a0, a1, a2, a3,
                                        bf[ntp][sub*2], bf[ntp][sub*2+1]);
                    }
                }
            }
        }
        cs = cs + 1; if (cs >= NSTAGE) cs -= NSTAGE;
    }

    // ---- epilogue ----
#pragma unroll
    for (int mt = 0; mt < 4; mt++) {
        const int row0 = bm*BM + warpM*64 + mt*16 + gid;
#pragma unroll
        for (int nt = 0; nt < 4; nt++) {
            const int col = bn*BN + warpN*32 + nt*8 + tig*2;
            const float bz0 = bias[col], bz1 = bias[col+1];
#pragma unroll
            for (int half = 0; half < 2; half++) {
                const int row = row0 + half*8;
                float v0 = acc[mt][nt][half*2+0] + bz0;
                float v1 = acc[mt][nt][half*2+1] + bz1;
                if (mode == 1) {
                    *(float2*)(C + (size_t)row*N + col) = make_float2(v0, v1);
                } else {
                    const int sel = col >> 10;
                    if (sel == 0) { v0 *= 0.125f; v1 *= 0.125f; }  // pre-scale Q
                    const int d2  = col & 1023;
                    const int h   = d2 >> 6;
                    const int dk  = d2 & 63;
                    const int b   = row >> 11;
                    const int s   = row & 2047;
                    __half* dst = (sel == 0) ? g_q : (sel == 1) ? g_k : g_v;
                    *(__half2*)(dst + ((size_t)(((b<<4)+h)*SEQ + s))*DK + dk)
                        = __floats2half2_rn(v0, v1);
                }
            }
        }
    }
}

// ===========================================================================
// fp16 tensor-core causal flash attention (mma.m16n8k16, fp32 softmax/accum).
// Unchanged from Round 11.
// ===========================================================================
#define AT_OPB (64*72*2)                       // 9216 B per operand per stage
#define AT_STAGEB (2*AT_OPB)                   // 18432 B
#define AT_NSTAGE 3
#define AT_SMEM_BYTES (AT_NSTAGE*AT_STAGEB)    // 55296 B

__global__ __launch_bounds__(256, 2)
void flash_attn_mma()
{
    extern __shared__ char atm[];
    const uint32_t sbase = smem_u32(atm);

    const int qt  = (int)gridDim.x - 1 - (int)blockIdx.x;   // heavy tiles first
    const int bh  = blockIdx.y;
    const int tid = threadIdx.x;
    const int w    = tid >> 5;
    const int lane = tid & 31;
    const int gid  = lane >> 2;
    const int tig  = lane & 3;

    const int r0  = w*16 + gid;
    const int qg0 = qt*128 + r0;
    const int qg1 = qg0 + 8;

    const int k_row  = (lane & 7) + ((lane >> 4) & 1)*8;   // QK (non-trans)
    const int k_colB = ((lane >> 3) & 1)*16;
    const int v_row  = (lane & 7) + ((lane >> 3) & 1)*8;   // PV (trans)
    const int v_colB = (lane >> 4)*16;

    const __half* qb = g_q + (size_t)(bh*SEQ + qt*128)*DK;
    uint32_t qa[4][4];
#pragma unroll
    for (int ks = 0; ks < 4; ks++) {
        qa[ks][0] = *(const uint32_t*)(qb + (size_t)r0*DK     + ks*16 + 2*tig);
        qa[ks][1] = *(const uint32_t*)(qb + (size_t)(r0+8)*DK + ks*16 + 2*tig);
        qa[ks][2] = *(const uint32_t*)(qb + (size_t)r0*DK     + ks*16 + 2*tig + 8);
        qa[ks][3] = *(const uint32_t*)(qb + (size_t)(r0+8)*DK + ks*16 + 2*tig + 8);
    }

    float o[8][4];
#pragma unroll
    for (int dt = 0; dt < 8; dt++)
#pragma unroll
        for (int r = 0; r < 4; r++) o[dt][r] = 0.f;
    float m0 = -1e30f, m1 = -1e30f, l0 = 0.f, l1 = 0.f;

    const int nkt = 2*qt + 2;
    const __half* kb0 = g_k + (size_t)bh*SEQ*DK;
    const __half* vb0 = g_v + (size_t)bh*SEQ*DK;

    auto copy_kv = [&](int kt, int stage) {
        const uint32_t kbuf = sbase + (uint32_t)stage*AT_STAGEB;
        const uint32_t vbuf = kbuf + AT_OPB;
        const __half* kb = kb0 + (size_t)kt*64*DK;
        const __half* vb = vb0 + (size_t)kt*64*DK;
#pragma unroll
        for (int i = 0; i < 2; i++) {
            const int idx = tid + i*256;
            const int row = idx >> 3;            // 0..63
            const int c8  = idx & 7;
            const uint32_t soff = (uint32_t)(row*144 + c8*16);
            cp_async16(kbuf + soff, kb + row*DK + c8*8);
            cp_async16(vbuf + soff, vb + row*DK + c8*8);
        }
        cp_commit();
    };

    copy_kv(0, 0);
    if (nkt > 1) copy_kv(1, 1);

    int cs = 0;
    for (int kt = 0; kt < nkt; kt++) {
        if (kt + 1 < nkt) {
            asm volatile("cp.async.wait_group 1;");
        } else {
            asm volatile("cp.async.wait_group 0;");
        }
        __syncthreads();

        if (kt + 2 < nkt) {
            int ps = cs + 2; if (ps >= AT_NSTAGE) ps -= AT_NSTAGE;
            copy_kv(kt + 2, ps);
        }

        const uint32_t kstage = sbase + (uint32_t)cs*AT_STAGEB;
        const uint32_t vstage = kstage + AT_OPB;

        // ---- S = Q K^T (scale folded into Q) ----
        float s[8][4];
#pragma unroll
        for (int nt = 0; nt < 8; nt++)
#pragma unroll
            for (int r = 0; r < 4; r++) s[nt][r] = 0.f;

        const uint32_t kAddr = kstage + (uint32_t)(k_row*144 + k_colB);
#pragma unroll
        for (int ks = 0; ks < 4; ks++) {
            const uint32_t ko = ks*32;
#pragma unroll
            for (int p = 0; p < 4; p++) {
                uint32_t b00, b01, b10, b11;
                ldsm_x4(b00, b01, b10, b11,
                        kAddr + (uint32_t)p*16*144 + ko);
                mma_f16_16x8x16(s[2*p][0], s[2*p][1], s[2*p][2], s[2*p][3],
                                qa[ks][0], qa[ks][1], qa[ks][2], qa[ks][3],
                                b00, b01);
                mma_f16_16x8x16(s[2*p+1][0], s[2*p+1][1],
                                s[2*p+1][2], s[2*p+1][3],
                                qa[ks][0], qa[ks][1], qa[ks][2], qa[ks][3],
                                b10, b11);
            }
        }

        // ---- causal mask ----
        if (kt >= 2*qt) {
#pragma unroll
            for (int nt = 0; nt < 8; nt++) {
                const int kg = kt*64 + nt*8 + 2*tig;
                if (kg     > qg0) s[nt][0] = -1e30f;
                if (kg + 1 > qg0) s[nt][1] = -1e30f;
                if (kg     > qg1) s[nt][2] = -1e30f;
                if (kg + 1 > qg1) s[nt][3] = -1e30f;
            }
        }

        // ---- online softmax (fp32) ----
        float t0 = -1e30f, t1 = -1e30f;
#pragma unroll
        for (int nt = 0; nt < 8; nt++) {
            t0 = fmaxf(t0, fmaxf(s[nt][0], s[nt][1]));
            t1 = fmaxf(t1, fmaxf(s[nt][2], s[nt][3]));
        }
        t0 = fmaxf(t0, SHFL_XOR(t0, 1)); t0 = fmaxf(t0, SHFL_XOR(t0, 2));
        t1 = fmaxf(t1, SHFL_XOR(t1, 1)); t1 = fmaxf(t1, SHFL_XOR(t1, 2));
        const float m0n = fmaxf(m0, t0), m1n = fmaxf(m1, t1);
        const float c0 = __expf(m0 - m0n), c1 = __expf(m1 - m1n);
        m0 = m0n; m1 = m1n;

        float sum0 = 0.f, sum1 = 0.f;
#pragma unroll
        for (int nt = 0; nt < 8; nt++) {
            s[nt][0] = __expf(s[nt][0] - m0);
            s[nt][1] = __expf(s[nt][1] - m0);
            s[nt][2] = __expf(s[nt][2] - m1);
            s[nt][3] = __expf(s[nt][3] - m1);
            sum0 += s[nt][0] + s[nt][1];
            sum1 += s[nt][2] + s[nt][3];
        }
        sum0 += SHFL_XOR(sum0, 1); sum0 += SHFL_XOR(sum0, 2);
        sum1 += SHFL_XOR(sum1, 1); sum1 += SHFL_XOR(sum1, 2);
        l0 = l0*c0 + sum0;
        l1 = l1*c1 + sum1;
#pragma unroll
        for (int dt = 0; dt < 8; dt++) {
            o[dt][0] *= c0; o[dt][1] *= c0;
            o[dt][2] *= c1; o[dt][3] *= c1;
        }

        // ---- O += P V (P A-frags = score C-frags; V via ldmatrix.trans) ----
        const uint32_t vAddr = vstage + (uint32_t)(v_row*144 + v_colB);
#pragma unroll
        for (int kp = 0; kp < 4; kp++) {
            const uint32_t pa0 = h2pack(s[2*kp  ][0], s[2*kp  ][1]);
            const uint32_t pa1 = h2pack(s[2*kp  ][2], s[2*kp  ][3]);
            const uint32_t pa2 = h2pack(s[2*kp+1][0], s[2*kp+1][1]);
            const uint32_t pa3 = h2pack(s[2*kp+1][2], s[2*kp+1][3]);
#pragma unroll
            for (int g = 0; g < 4; g++) {
                uint32_t v00, v01, v10, v11;
                ldsm_x4_t(v00, v01, v10, v11,
                          vAddr + (uint32_t)kp*16*144 + g*32);
                mma_f16_16x8x16(o[2*g][0], o[2*g][1], o[2*g][2], o[2*g][3],
                                pa0, pa1, pa2, pa3, v00, v01);
                mma_f16_16x8x16(o[2*g+1][0], o[2*g+1][1],
                                o[2*g+1][2], o[2*g+1][3],
                                pa0, pa1, pa2, pa3, v10, v11);
            }
        }

        cs = cs + 1; if (cs >= AT_NSTAGE) cs -= AT_NSTAGE;
    }

    // ---- finalize: O /= l, fp16-round (O-proj input), write [B,S,D] ----
    const float inv0 = 1.f / l0, inv1 = 1.f / l1;
    const int b = bh >> 4, h = bh & 15;
    __half* ob0 = g_attn + (size_t)(b*SEQ + qg0)*DMODEL + h*DK;
    __half* ob1 = g_attn + (size_t)(b*SEQ + qg1)*DMODEL + h*DK;
#pragma unroll
    for (int dt = 0; dt < 8; dt++) {
        const int d = dt*8 + 2*tig;
        *(__half2*)(ob0 + d) = __floats2half2_rn(o[dt][0]*inv0, o[dt][1]*inv0);
        *(__half2*)(ob1 + d) = __floats2half2_rn(o[dt][2]*inv1, o[dt][3]*inv1);
    }
}

// ---------------------------------------------------------------------------
// Launch.  Inputs: x, mask, w_qkv_w, w_qkv_b, w_o_w, w_o_b
// ---------------------------------------------------------------------------
extern "C" void kernel_launch(void* const* d_in, const int* in_sizes, int n_in,
                              void* d_out, int out_size)
{
    const float* x      = (const float*)d_in[0];
    const float* wqkv   = (const float*)d_in[2];
    const float* bqkv   = (const float*)d_in[3];
    const float* wo     = (const float*)d_in[4];
    const float* bo     = (const float*)d_in[5];
    float* out = (float*)d_out;

    __half *p_attn, *p_x, *p_wqkv, *p_wo;
    cudaGetSymbolAddress((void**)&p_attn, g_attn);
    cudaGetSymbolAddress((void**)&p_x,    g_x);
    cudaGetSymbolAddress((void**)&p_wqkv, g_wqkv);
    cudaGetSymbolAddress((void**)&p_wo,   g_wo);

    cudaFuncSetAttribute(mma_gemm, cudaFuncAttributeMaxDynamicSharedMemorySize,
                         GEMM_SMEM_BYTES);
    cudaFuncSetAttribute(flash_attn_mma,
                         cudaFuncAttributeMaxDynamicSharedMemorySize,
                         AT_SMEM_BYTES);

    // 0) pre-round inputs/weights to fp16 (single launch)
    roundcopy_all<<<2048, 256>>>((const float4*)x, (const float4*)wqkv,
                                 (const float4*)wo);

    // 1) QKV projection -> g_q (x0.125) / g_k / g_v (fp16)
    {
        dim3 grid(3*DMODEL/BN, M_TOK/BM);   // (24, 32)
        mma_gemm<<<grid, 256, GEMM_SMEM_BYTES>>>(p_x, p_wqkv, bqkv, nullptr,
                                                 M_TOK, 3*DMODEL, DMODEL, 0);
    }
    // 2) Causal flash attention -> g_attn (fp16)
    {
        dim3 grid(SEQ/128, BATCH*NHEADS);   // (16, 32)
        flash_attn_mma<<<grid, 256, AT_SMEM_BYTES>>>();
    }
    // 3) Output projection -> d_out (fp32)
    {
        dim3 grid(DMODEL/BN, M_TOK/BM);     // (8, 32)
        mma_gemm<<<grid, 256, GEMM_SMEM_BYTES>>>(p_attn, p_wo, bo, out,
                                                 M_TOK, DMODEL, DMODEL, 1);
    }
}

// round 15
// speedup vs baseline: 10.7813x; 1.0106x over previous
#include <cuda_runtime.h>
#include <cuda_fp16.h>
#include <cstdint>

// Problem constants
#define BATCH 2
#define SEQ   2048
#define DMODEL 1024
#define NHEADS 16
#define DK 64
#define M_TOK (BATCH*SEQ)          // 4096

// Q pre-scale: (1/sqrt(64)) * log2(e)  -> scores arrive in log2 units
#define QSCALE 0.1803368801111855f

// Scratch (no allocations allowed -> __device__ globals).  All fp16.
__device__ __half g_q[BATCH*NHEADS*SEQ*DK];     // pre-scaled by QSCALE
__device__ __half g_k[BATCH*NHEADS*SEQ*DK];
__device__ __half g_v[BATCH*NHEADS*SEQ*DK];
__device__ __half g_attn[M_TOK*DMODEL];
__device__ __half g_x[M_TOK*DMODEL];
__device__ __half g_wqkv[3*DMODEL*DMODEL];
__device__ __half g_wo[DMODEL*DMODEL];

// ---------------------------------------------------------------------------
// helpers
// ---------------------------------------------------------------------------
__device__ __forceinline__ uint32_t smem_u32(const void* p) {
    uint32_t a;
    asm("{ .reg .u64 t; cvta.to.shared.u64 t, %1; cvt.u32.u64 %0, t; }"
        : "=r"(a) : "l"(p));
    return a;
}
__device__ __forceinline__ void cp_async16(uint32_t saddr, const void* gaddr) {
    asm volatile("cp.async.cg.shared.global [%0], [%1], 16;"
                 :: "r"(saddr), "l"(gaddr));
}
__device__ __forceinline__ void cp_commit() {
    asm volatile("cp.async.commit_group;");
}
__device__ __forceinline__ void ldsm_x4(uint32_t& r0, uint32_t& r1,
                                        uint32_t& r2, uint32_t& r3, uint32_t addr) {
    asm volatile("ldmatrix.sync.aligned.m8n8.x4.shared.b16 {%0,%1,%2,%3}, [%4];"
                 : "=r"(r0), "=r"(r1), "=r"(r2), "=r"(r3) : "r"(addr));
}
__device__ __forceinline__ void ldsm_x4_t(uint32_t& r0, uint32_t& r1,
                                          uint32_t& r2, uint32_t& r3, uint32_t addr) {
    asm volatile("ldmatrix.sync.aligned.m8n8.x4.trans.shared.b16 {%0,%1,%2,%3}, [%4];"
                 : "=r"(r0), "=r"(r1), "=r"(r2), "=r"(r3) : "r"(addr));
}
__device__ __forceinline__ uint32_t h2pack(float lo, float hi) {
    __half2 h = __floats2half2_rn(lo, hi);   // .x = lo (bits 0-15)
    return *(uint32_t*)&h;
}
__device__ __forceinline__ float ex2(float x) {
    float y;
    asm("ex2.approx.f32 %0, %1;" : "=f"(y) : "f"(x));
    return y;
}
__device__ __forceinline__ void mma_f16_16x8x16(
    float& d0, float& d1, float& d2, float& d3,
    uint32_t a0, uint32_t a1, uint32_t a2, uint32_t a3,
    uint32_t b0, uint32_t b1)
{
    asm volatile(
        "mma.sync.aligned.m16n8k16.row.col.f32.f16.f16.f32 "
        "{%0,%1,%2,%3}, {%4,%5,%6,%7}, {%8,%9}, {%0,%1,%2,%3};"
        : "+f"(d0), "+f"(d1), "+f"(d2), "+f"(d3)
        : "r"(a0), "r"(a1), "r"(a2), "r"(a3), "r"(b0), "r"(b1));
}

#define SHFL_XOR(v, m) __shfl_xor_sync(0xffffffffu, v, m)

// ---------------------------------------------------------------------------
// Pre-pass (single launch): fp32 -> fp16 round for x, w_qkv, w_o.
// ---------------------------------------------------------------------------
#define N4_X    (M_TOK*DMODEL/4)            // 1048576
#define N4_WQKV (3*DMODEL*DMODEL/4)         // 786432
#define N4_WO   (DMODEL*DMODEL/4)           // 262144
#define N4_TOT  (N4_X + N4_WQKV + N4_WO)    // 2097152

__global__ __launch_bounds__(256)
void roundcopy_all(const float4* __restrict__ sx, const float4* __restrict__ swq,
                   const float4* __restrict__ swo)
{
    __half2 *dx  = (__half2*)g_x;
    __half2 *dwq = (__half2*)g_wqkv;
    __half2 *dwo = (__half2*)g_wo;
    for (int i = blockIdx.x*blockDim.x + threadIdx.x; i < N4_TOT;
         i += gridDim.x*blockDim.x) {
        const float4* s; __half2* d; int j;
        if (i < N4_X)                { s = sx;  d = dx;  j = i; }
        else if (i < N4_X + N4_WQKV) { s = swq; d = dwq; j = i - N4_X; }
        else                         { s = swo; d = dwo; j = i - N4_X - N4_WQKV; }
        float4 v = s[j];
        d[2*j]   = __floats2half2_rn(v.x, v.y);
        d[2*j+1] = __floats2half2_rn(v.z, v.w);
    }
}

// ===========================================================================
// fp16 tensor-core GEMM (unchanged from R13 except QSCALE): C = A@B^T + bias.
// 128x128 tile, BK=64, 3-stage cp.async pipeline, ldmatrix fragments.
// mode 0: scatter fp16 into g_q (xQSCALE) / g_k / g_v; mode 1: fp32 C write.
// ===========================================================================
#define BM 128
#define BN 128
#define ROWB 144                         // bytes per smem row (72 halves)
#define OPB  (128*ROWB)                  // 18432 B per operand per stage
#define STAGEB (2*OPB)                   // 36864 B
#define NSTAGE 3
#define GEMM_SMEM_BYTES (NSTAGE*STAGEB)  // 110592 B

__global__ __launch_bounds__(256)
void mma_gemm(const __half* __restrict__ A, const __half* __restrict__ B,
              const float* __restrict__ bias, float* __restrict__ C,
              int M, int N, int K, int mode)
{
    extern __shared__ char smx[];
    const uint32_t sbase = smem_u32(smx);

    const int tid = threadIdx.x;
    const int wid = tid >> 5;
    const int lane = tid & 31;
    const int gid = lane >> 2;
    const int tig = lane & 3;
    const int warpM = wid >> 2;
    const int warpN = wid & 3;
    const int bm = blockIdx.y, bn = blockIdx.x;

    const __half* Abase = A + (size_t)(bm*BM)*K;
    const __half* Bbase = B + (size_t)(bn*BN)*K;

    const int a_row  = lane & 15;
    const int a_colB = (lane >> 4)*16;
    const int b_row  = (lane & 7) + ((lane >> 4) & 1)*8;
    const int b_colB = ((lane >> 3) & 1)*16;

    float acc[4][4][4];
#pragma unroll
    for (int i = 0; i < 4; i++)
#pragma unroll
        for (int j = 0; j < 4; j++)
#pragma unroll
            for (int r = 0; r < 4; r++) acc[i][j][r] = 0.f;

    const int NC = K / 64;

    auto copy_stage = [&](int c, int st) {
        const uint32_t abuf = sbase + (uint32_t)st*STAGEB;
        const uint32_t bbuf = abuf + OPB;
        const int k0 = c * 64;
#pragma unroll
        for (int i = 0; i < 4; i++) {
            const int idx = tid + i*256;
            const int row = idx >> 3;            // 0..127
            const int c8  = idx & 7;
            const uint32_t soff = (uint32_t)(row*ROWB + c8*16);
            cp_async16(abuf + soff, Abase + (size_t)row*K + k0 + c8*8);
            cp_async16(bbuf + soff, Bbase + (size_t)row*K + k0 + c8*8);
        }
        cp_commit();
    };

    copy_stage(0, 0);
    copy_stage(1, 1);

    int cs = 0;
    for (int c = 0; c < NC; c++) {
        if (c + 1 < NC) {
            asm volatile("cp.async.wait_group 1;");
        } else {
            asm volatile("cp.async.wait_group 0;");
        }
        __syncthreads();

        if (c + 2 < NC) {
            int ps = cs + 2; if (ps >= NSTAGE) ps -= NSTAGE;
            copy_stage(c + 2, ps);
        }

        const uint32_t stage_base = sbase + (uint32_t)cs*STAGEB;
        const uint32_t aAddr = stage_base
            + (uint32_t)((warpM*64 + a_row)*ROWB + a_colB);
        const uint32_t bAddr = stage_base + OPB
            + (uint32_t)((warpN*32 + b_row)*ROWB + b_colB);

#pragma unroll
        for (int ks = 0; ks < 4; ks++) {
            const uint32_t ko = ks*32;           // 16 halves
            uint32_t bf[2][4];
            ldsm_x4(bf[0][0], bf[0][1], bf[0][2], bf[0][3], bAddr + ko);
            ldsm_x4(bf[1][0], bf[1][1], bf[1][2], bf[1][3],
                    bAddr + 16*ROWB + ko);
#pragma unroll
            for (int mt = 0; mt < 4; mt++) {
                uint32_t a0, a1, a2, a3;
                ldsm_x4(a0, a1, a2, a3, aAddr + (uint32_t)mt*16*ROWB + ko);
#pragma unroll
                for (int ntp = 0; ntp < 2; ntp++) {
#pragma unroll
                    for (int sub = 0; sub < 2; sub++) {
                        const int nt = ntp*2 + sub;
                        mma_f16_16x8x16(acc[mt][nt][0], acc[mt][nt][1],
                                        acc[mt][nt][2], acc[mt][nt][3],
                                        a0, a1, a2, a3,
                                        bf[ntp][sub*2], bf[ntp][sub*2+1]);
                    }
                }
            }
        }
        cs = cs + 1; if (cs >= NSTAGE) cs -= NSTAGE;
    }

    // ---- epilogue ----
#pragma unroll
    for (int mt = 0; mt < 4; mt++) {
        const int row0 = bm*BM + warpM*64 + mt*16 + gid;
#pragma unroll
        for (int nt = 0; nt < 4; nt++) {
            const int col = bn*BN + warpN*32 + nt*8 + tig*2;
            const float bz0 = bias[col], bz1 = bias[col+1];
#pragma unroll
            for (int half = 0; half < 2; half++) {
                const int row = row0 + half*8;
                float v0 = acc[mt][nt][half*2+0] + bz0;
                float v1 = acc[mt][nt][half*2+1] + bz1;
                if (mode == 1) {
                    *(float2*)(C + (size_t)row*N + col) = make_float2(v0, v1);
                } else {
                    const int sel = col >> 10;
                    if (sel == 0) { v0 *= QSCALE; v1 *= QSCALE; }
                    const int d2  = col & 1023;
                    const int h   = d2 >> 6;
                    const int dk  = d2 & 63;
                    const int b   = row >> 11;
                    const int s   = row & 2047;
                    __half* dst = (sel == 0) ? g_q : (sel == 1) ? g_k : g_v;
                    *(__half2*)(dst + ((size_t)(((b<<4)+h)*SEQ + s))*DK + dk)
                        = __floats2half2_rn(v0, v1);
                }
            }
        }
    }
}

// ===========================================================================
// fp16 tensor-core causal flash attention (mma.m16n8k16).
// Scores arrive in log2 units (QSCALE includes log2e) -> softmax uses raw
// ex2.approx, no per-element multiply. Row-sum l kept lane-partial, reduced
// once at finalize (corrections are quad-uniform because m is quad-reduced).
// ===========================================================================
#define AT_OPB (64*72*2)                       // 9216 B per operand per stage
#define AT_STAGEB (2*AT_OPB)                   // 18432 B
#define AT_NSTAGE 3
#define AT_SMEM_BYTES (AT_NSTAGE*AT_STAGEB)    // 55296 B

__global__ __launch_bounds__(256, 2)
void flash_attn_mma()
{
    extern __shared__ char atm[];
    const uint32_t sbase = smem_u32(atm);

    const int qt  = (int)gridDim.x - 1 - (int)blockIdx.x;   // heavy tiles first
    const int bh  = blockIdx.y;
    const int tid = threadIdx.x;
    const int w    = tid >> 5;
    const int lane = tid & 31;
    const int gid  = lane >> 2;
    const int tig  = lane & 3;

    const int r0  = w*16 + gid;
    const int qg0 = qt*128 + r0;
    const int qg1 = qg0 + 8;

    const int k_row  = (lane & 7) + ((lane >> 4) & 1)*8;   // QK (non-trans)
    const int k_colB = ((lane >> 3) & 1)*16;
    const int v_row  = (lane & 7) + ((lane >> 3) & 1)*8;   // PV (trans)
    const int v_colB = (lane >> 4)*16;

    const __half* qb = g_q + (size_t)(bh*SEQ + qt*128)*DK;
    uint32_t qa[4][4];
#pragma unroll
    for (int ks = 0; ks < 4; ks++) {
        qa[ks][0] = *(const uint32_t*)(qb + (size_t)r0*DK     + ks*16 + 2*tig);
        qa[ks][1] = *(const uint32_t*)(qb + (size_t)(r0+8)*DK + ks*16 + 2*tig);
        qa[ks][2] = *(const uint32_t*)(qb + (size_t)r0*DK     + ks*16 + 2*tig + 8);
        qa[ks][3] = *(const uint32_t*)(qb + (size_t)(r0+8)*DK + ks*16 + 2*tig + 8);
    }

    float o[8][4];
#pragma unroll
    for (int dt = 0; dt < 8; dt++)
#pragma unroll
        for (int r = 0; r < 4; r++) o[dt][r] = 0.f;
    float m0 = -1e30f, m1 = -1e30f, l0 = 0.f, l1 = 0.f;   // l: lane-partial

    const int nkt = 2*qt + 2;
    const __half* kb0 = g_k + (size_t)bh*SEQ*DK;
    const __half* vb0 = g_v + (size_t)bh*SEQ*DK;

    auto copy_kv = [&](int kt, int stage) {
        const uint32_t kbuf = sbase + (uint32_t)stage*AT_STAGEB;
        const uint32_t vbuf = kbuf + AT_OPB;
        const __half* kb = kb0 + (size_t)kt*64*DK;
        const __half* vb = vb0 + (size_t)kt*64*DK;
#pragma unroll
        for (int i = 0; i < 2; i++) {
            const int idx = tid + i*256;
            const int row = idx >> 3;            // 0..63
            const int c8  = idx & 7;
            const uint32_t soff = (uint32_t)(row*144 + c8*16);
            cp_async16(kbuf + soff, kb + row*DK + c8*8);
            cp_async16(vbuf + soff, vb + row*DK + c8*8);
        }
        cp_commit();
    };

    copy_kv(0, 0);
    if (nkt > 1) copy_kv(1, 1);

    int cs = 0;
    for (int kt = 0; kt < nkt; kt++) {
        if (kt + 1 < nkt) {
            asm volatile("cp.async.wait_group 1;");
        } else {
            asm volatile("cp.async.wait_group 0;");
        }
        __syncthreads();

        if (kt + 2 < nkt) {
            int ps = cs + 2; if (ps >= AT_NSTAGE) ps -= AT_NSTAGE;
            copy_kv(kt + 2, ps);
        }

        const uint32_t kstage = sbase + (uint32_t)cs*AT_STAGEB;
        const uint32_t vstage = kstage + AT_OPB;

        // ---- S = Q K^T (log2-domain scale folded into Q) ----
        float s[8][4];
#pragma unroll
        for (int nt = 0; nt < 8; nt++)
#pragma unroll
            for (int r = 0; r < 4; r++) s[nt][r] = 0.f;

        const uint32_t kAddr = kstage + (uint32_t)(k_row*144 + k_colB);
#pragma unroll
        for (int ks = 0; ks < 4; ks++) {
            const uint32_t ko = ks*32;
#pragma unroll
            for (int p = 0; p < 4; p++) {
                uint32_t b00, b01, b10, b11;
                ldsm_x4(b00, b01, b10, b11,
                        kAddr + (uint32_t)p*16*144 + ko);
                mma_f16_16x8x16(s[2*p][0], s[2*p][1], s[2*p][2], s[2*p][3],
                                qa[ks][0], qa[ks][1], qa[ks][2], qa[ks][3],
                                b00, b01);
                mma_f16_16x8x16(s[2*p+1][0], s[2*p+1][1],
                                s[2*p+1][2], s[2*p+1][3],
                                qa[ks][0], qa[ks][1], qa[ks][2], qa[ks][3],
                                b10, b11);
            }
        }

        // ---- causal mask ----
        if (kt >= 2*qt) {
#pragma unroll
            for (int nt = 0; nt < 8; nt++) {
                const int kg = kt*64 + nt*8 + 2*tig;
                if (kg     > qg0) s[nt][0] = -1e30f;
                if (kg + 1 > qg0) s[nt][1] = -1e30f;
                if (kg     > qg1) s[nt][2] = -1e30f;
                if (kg + 1 > qg1) s[nt][3] = -1e30f;
            }
        }

        // ---- online softmax (log2 domain, fp32) ----
        float t0 = -1e30f, t1 = -1e30f;
#pragma unroll
        for (int nt = 0; nt < 8; nt++) {
            t0 = fmaxf(t0, fmaxf(s[nt][0], s[nt][1]));
            t1 = fmaxf(t1, fmaxf(s[nt][2], s[nt][3]));
        }
        t0 = fmaxf(t0, SHFL_XOR(t0, 1)); t0 = fmaxf(t0, SHFL_XOR(t0, 2));
        t1 = fmaxf(t1, SHFL_XOR(t1, 1)); t1 = fmaxf(t1, SHFL_XOR(t1, 2));
        const float m0n = fmaxf(m0, t0), m1n = fmaxf(m1, t1);
        const float c0 = ex2(m0 - m0n), c1 = ex2(m1 - m1n);
        m0 = m0n; m1 = m1n;

        float sum0 = 0.f, sum1 = 0.f;
#pragma unroll
        for (int nt = 0; nt < 8; nt++) {
            s[nt][0] = ex2(s[nt][0] - m0);
            s[nt][1] = ex2(s[nt][1] - m0);
            s[nt][2] = ex2(s[nt][2] - m1);
            s[nt][3] = ex2(s[nt][3] - m1);
            sum0 += s[nt][0] + s[nt][1];
            sum1 += s[nt][2] + s[nt][3];
        }
        l0 = l0*c0 + sum0;        // lane-partial; reduced at finalize
        l1 = l1*c1 + sum1;
#pragma unroll
        for (int dt = 0; dt < 8; dt++) {
            o[dt][0] *= c0; o[dt][1] *= c0;
            o[dt][2] *= c1; o[dt][3] *= c1;
        }

        // ---- O += P V (P A-frags = score C-frags; V via ldmatrix.trans) ----
        const uint32_t vAddr = vstage + (uint32_t)(v_row*144 + v_colB);
#pragma unroll
        for (int kp = 0; kp < 4; kp++) {
            const uint32_t pa0 = h2pack(s[2*kp  ][0], s[2*kp  ][1]);
            const uint32_t pa1 = h2pack(s[2*kp  ][2], s[2*kp  ][3]);
            const uint32_t pa2 = h2pack(s[2*kp+1][0], s[2*kp+1][1]);
            const uint32_t pa3 = h2pack(s[2*kp+1][2], s[2*kp+1][3]);
#pragma unroll
            for (int g = 0; g < 4; g++) {
                uint32_t v00, v01, v10, v11;
                ldsm_x4_t(v00, v01, v10, v11,
                          vAddr + (uint32_t)kp*16*144 + g*32);
                mma_f16_16x8x16(o[2*g][0], o[2*g][1], o[2*g][2], o[2*g][3],
                                pa0, pa1, pa2, pa3, v00, v01);
                mma_f16_16x8x16(o[2*g+1][0], o[2*g+1][1],
                                o[2*g+1][2], o[2*g+1][3],
                                pa0, pa1, pa2, pa3, v10, v11);
            }
        }

        cs = cs + 1; if (cs >= AT_NSTAGE) cs -= AT_NSTAGE;
    }

    // ---- finalize: reduce l across quad, O /= l, write fp16 [B,S,D] ----
    l0 += SHFL_XOR(l0, 1); l0 += SHFL_XOR(l0, 2);
    l1 += SHFL_XOR(l1, 1); l1 += SHFL_XOR(l1, 2);
    const float inv0 = 1.f / l0, inv1 = 1.f / l1;
    const int b = bh >> 4, h = bh & 15;
    __half* ob0 = g_attn + (size_t)(b*SEQ + qg0)*DMODEL + h*DK;
    __half* ob1 = g_attn + (size_t)(b*SEQ + qg1)*DMODEL + h*DK;
#pragma unroll
    for (int dt = 0; dt < 8; dt++) {
        const int d = dt*8 + 2*tig;
        *(__half2*)(ob0 + d) = __floats2half2_rn(o[dt][0]*inv0, o[dt][1]*inv0);
        *(__half2*)(ob1 + d) = __floats2half2_rn(o[dt][2]*inv1, o[dt][3]*inv1);
    }
}

// ---------------------------------------------------------------------------
// Launch.  Inputs: x, mask, w_qkv_w, w_qkv_b, w_o_w, w_o_b
// ---------------------------------------------------------------------------
extern "C" void kernel_launch(void* const* d_in, const int* in_sizes, int n_in,
                              void* d_out, int out_size)
{
    const float* x      = (const float*)d_in[0];
    const float* wqkv   = (const float*)d_in[2];
    const float* bqkv   = (const float*)d_in[3];
    const float* wo     = (const float*)d_in[4];
    const float* bo     = (const float*)d_in[5];
    float* out = (float*)d_out;

    __half *p_attn, *p_x, *p_wqkv, *p_wo;
    cudaGetSymbolAddress((void**)&p_attn, g_attn);
    cudaGetSymbolAddress((void**)&p_x,    g_x);
    cudaGetSymbolAddress((void**)&p_wqkv, g_wqkv);
    cudaGetSymbolAddress((void**)&p_wo,   g_wo);

    cudaFuncSetAttribute(mma_gemm, cudaFuncAttributeMaxDynamicSharedMemorySize,
                         GEMM_SMEM_BYTES);
    cudaFuncSetAttribute(flash_attn_mma,
                         cudaFuncAttributeMaxDynamicSharedMemorySize,
                         AT_SMEM_BYTES);

    // 0) pre-round inputs/weights to fp16 (single launch)
    roundcopy_all<<<2048, 256>>>((const float4*)x, (const float4*)wqkv,
                                 (const float4*)wo);

    // 1) QKV projection -> g_q (xQSCALE) / g_k / g_v (fp16)
    {
        dim3 grid(3*DMODEL/BN, M_TOK/BM);   // (24, 32)
        mma_gemm<<<grid, 256, GEMM_SMEM_BYTES>>>(p_x, p_wqkv, bqkv, nullptr,
                                                 M_TOK, 3*DMODEL, DMODEL, 0);
    }
    // 2) Causal flash attention -> g_attn (fp16)
    {
        dim3 grid(SEQ/128, BATCH*NHEADS);   // (16, 32)
        flash_attn_mma<<<grid, 256, AT_SMEM_BYTES>>>();
    }
    // 3) Output projection -> d_out (fp32)
    {
        dim3 grid(DMODEL/BN, M_TOK/BM);     // (8, 32)
        mma_gemm<<<grid, 256, GEMM_SMEM_BYTES>>>(p_attn, p_wo, bo, out,
                                                 M_TOK, DMODEL, DMODEL, 1);
    }
}